// round 2
// baseline (speedup 1.0000x reference)
#include <cuda_runtime.h>
#include <cuda_bf16.h>
#include <cstdint>

// ---------------------------------------------------------------------------
// WordSpeechContinuousFusion  (B=16, S=2048, D=512 nominal; shapes derived)
//
// Pipeline:
//   k_score : p[i]=frame_i . w1,  q[i]=frame_i . w2          (1 read of frames)
//   k_scan  : per-batch block scan of start flags -> word_start[], n_words[]
//   k_gemm  : Y = frame @ w_comb   (dense fp32 SGEMM, independent of scan)
//   k_avg   : out[b,s] = mean(Y[b, start_s:end_s]) + b_comb  (valid), else 0
//
// Key identity: mean(frames) @ W == mean(frames @ W)  (exact up to fp32
// rounding), which decouples the GEMM from the data-dependent segmentation.
//
// Scratch: __device__ globals (allocation-free contract).
// ---------------------------------------------------------------------------

#define MAX_BS   65536               // max B*S
#define MAX_B    4096
#define Y_ELEMS  ((size_t)1 << 24)   // 16.8M floats == BS*D for this family

__device__ float g_p[MAX_BS];
__device__ float g_q[MAX_BS];
__device__ float g_Y[Y_ELEMS];
__device__ int   g_wstart[MAX_BS + MAX_B + 1];
__device__ int   g_nw[MAX_B];

// ---------------------------------------------------------------------------
// Kernel 1: per-frame dot products with the two halves of w_score.
// One warp per frame; float4 vector loads; warp shuffle reduce.
// ---------------------------------------------------------------------------
__global__ void k_score(const float* __restrict__ x,
                        const float* __restrict__ wscore,
                        int D, int BS)
{
    int gw   = (blockIdx.x * blockDim.x + threadIdx.x) >> 5;
    int lane = threadIdx.x & 31;
    if (gw >= BS) return;

    const float4* f  = (const float4*)(x + (size_t)gw * D);
    const float4* w1 = (const float4*)(wscore);
    const float4* w2 = (const float4*)(wscore + D);
    int n4 = D >> 2;

    float a = 0.f, b = 0.f;
    for (int i = lane; i < n4; i += 32) {
        float4 xv = f[i];
        float4 w1v = w1[i];
        float4 w2v = w2[i];
        a += xv.x * w1v.x + xv.y * w1v.y + xv.z * w1v.z + xv.w * w1v.w;
        b += xv.x * w2v.x + xv.y * w2v.y + xv.z * w2v.z + xv.w * w2v.w;
    }
    #pragma unroll
    for (int o = 16; o; o >>= 1) {
        a += __shfl_xor_sync(0xffffffffu, a, o);
        b += __shfl_xor_sync(0xffffffffu, b, o);
    }
    if (lane == 0) { g_p[gw] = a; g_q[gw] = b; }
}

// ---------------------------------------------------------------------------
// Kernel 2: per-batch inclusive scan of start flags.
//   starts[0]=0; starts[t]=(score[t-1] <= 0.5), score[t-1]=p[t-1]+q[t]+b.
// Records word boundaries and n_words. One block per batch, 256 threads.
// Handles S up to 4096 (chunk <= 16).
// ---------------------------------------------------------------------------
__global__ void k_scan(const float* __restrict__ bscore_p,
                       int S, float* __restrict__ tail)
{
    const int T = 256;
    int b   = blockIdx.x;
    int tid = threadIdx.x;
    int chunk = (S + T - 1) / T;               // 8 for S=2048
    if (chunk > 16) chunk = 16;                // safety clamp (S <= 4096)

    const float* pb = g_p + (size_t)b * S;
    const float* qb = g_q + (size_t)b * S;
    float bsc = *bscore_p;

    int local[16];
    int sum = 0;
    for (int i = 0; i < chunk; i++) {
        int t = tid * chunk + i;
        int st = 0;
        if (t > 0 && t < S) {
            float sc = pb[t - 1] + qb[t] + bsc;
            st = (sc > 0.5f) ? 0 : 1;
        }
        sum += st;
        local[i] = sum;                        // inclusive within chunk
    }

    // warp inclusive scan of per-thread sums
    int lane = tid & 31, w = tid >> 5;
    int v = sum;
    #pragma unroll
    for (int o = 1; o < 32; o <<= 1) {
        int n = __shfl_up_sync(0xffffffffu, v, o);
        if (lane >= o) v += n;
    }
    __shared__ int wsum[8];
    __shared__ int woff[9];
    if (lane == 31) wsum[w] = v;
    __syncthreads();
    if (tid == 0) {
        int acc = 0;
        for (int i = 0; i < 8; i++) { woff[i] = acc; acc += wsum[i]; }
        woff[8] = acc;
    }
    __syncthreads();

    int excl = woff[w] + (v - sum);            // exclusive prefix of this thread
    int* wsb = g_wstart + (size_t)b * (S + 1);
    for (int i = 0; i < chunk; i++) {
        int t = tid * chunk + i;
        if (t < S) {
            int stflag = local[i] - (i ? local[i - 1] : 0);
            int seg = excl + local[i];
            if (t == 0 || stflag) wsb[seg] = t; // start of word `seg`
        }
    }
    if (tid == 0) {
        int nw = woff[8] + 1;
        wsb[nw] = S;                           // sentinel end
        g_nw[b] = nw;
        if (tail) tail[b] = (float)nw;
    }
}

// ---------------------------------------------------------------------------
// Kernel 3: Y = A @ W   (fp32 SGEMM, 128x128x8, 8x8 microtile, dbl-buffered)
// A: [M,K] row-major (frames), W: [K,N] row-major (w_comb), Y: [M,N].
// Assumes M%128==0, N%128==0, K%8==0 (holds for this problem family).
// ---------------------------------------------------------------------------
#define BM 128
#define BN 128
#define BK 8
__global__ __launch_bounds__(256, 2)
void k_gemm(const float* __restrict__ A, const float* __restrict__ W,
            int M, int N, int K)
{
    __shared__ float As[2][BK][BM];
    __shared__ float Bs[2][BK][BN];

    int bx = blockIdx.x;                       // N tile
    int by = blockIdx.y;                       // M tile
    int tid = threadIdx.x;
    int tx = tid & 15;                         // 0..15
    int ty = tid >> 4;                         // 0..15

    // A tile loaders: thread -> one float4 (row tid/2, col (tid&1)*4)
    int arow = tid >> 1;
    int acol = (tid & 1) * 4;
    // B tile loaders: thread -> one float4 (row tid/32, col (tid&31)*4)
    int brow = tid >> 5;
    int bcol = (tid & 31) * 4;

    const float* Ap = A + ((size_t)(by * BM + arow)) * K + acol;
    const float* Bp = W + (size_t)brow * N + bx * BN + bcol;

    float acc[8][8];
    #pragma unroll
    for (int i = 0; i < 8; i++)
        #pragma unroll
        for (int j = 0; j < 8; j++) acc[i][j] = 0.f;

    // preload tile 0
    float4 a4 = *(const float4*)Ap;
    float4 b4 = *(const float4*)Bp;
    As[0][acol + 0][arow] = a4.x;
    As[0][acol + 1][arow] = a4.y;
    As[0][acol + 2][arow] = a4.z;
    As[0][acol + 3][arow] = a4.w;
    *(float4*)&Bs[0][brow][bcol] = b4;
    __syncthreads();

    int buf = 0;
    for (int k0 = 0; k0 < K; k0 += BK) {
        bool more = (k0 + BK) < K;
        float4 na, nb;
        if (more) {
            na = *(const float4*)(Ap + (k0 + BK));
            nb = *(const float4*)(Bp + (size_t)(k0 + BK) * N);
        }
        #pragma unroll
        for (int k = 0; k < BK; k++) {
            float ra[8], rb[8];
            *(float4*)(ra + 0) = *(float4*)&As[buf][k][ty * 4];
            *(float4*)(ra + 4) = *(float4*)&As[buf][k][64 + ty * 4];
            *(float4*)(rb + 0) = *(float4*)&Bs[buf][k][tx * 4];
            *(float4*)(rb + 4) = *(float4*)&Bs[buf][k][64 + tx * 4];
            #pragma unroll
            for (int i = 0; i < 8; i++)
                #pragma unroll
                for (int j = 0; j < 8; j++)
                    acc[i][j] = fmaf(ra[i], rb[j], acc[i][j]);
        }
        if (more) {
            int nxt = buf ^ 1;
            As[nxt][acol + 0][arow] = na.x;
            As[nxt][acol + 1][arow] = na.y;
            As[nxt][acol + 2][arow] = na.z;
            As[nxt][acol + 3][arow] = na.w;
            *(float4*)&Bs[nxt][brow][bcol] = nb;
            __syncthreads();
            buf = nxt;
        }
    }

    // write out (to g_Y)
    #pragma unroll
    for (int i = 0; i < 8; i++) {
        int r = by * BM + ((i < 4) ? (ty * 4 + i) : (64 + ty * 4 + i - 4));
        float* crow = g_Y + (size_t)r * N + bx * BN;
        float4 v0 = make_float4(acc[i][0], acc[i][1], acc[i][2], acc[i][3]);
        float4 v1 = make_float4(acc[i][4], acc[i][5], acc[i][6], acc[i][7]);
        *(float4*)(crow + tx * 4)      = v0;
        *(float4*)(crow + 64 + tx * 4) = v1;
    }
}

// ---------------------------------------------------------------------------
// Kernel 4: segment-average of Y rows + bias; zero invalid rows.
// Grid (S, B), 128 threads, each thread owns D/512 float4 columns.
// ---------------------------------------------------------------------------
__global__ void k_avg(const float* __restrict__ bcomb,
                      float* __restrict__ out, int S, int D)
{
    int b = blockIdx.y;
    int s = blockIdx.x;
    int n4 = D >> 2;
    float4* orow = (float4*)(out + ((size_t)b * S + s) * D);

    int nw = g_nw[b];
    if (s >= nw) {
        for (int i = threadIdx.x; i < n4; i += blockDim.x)
            orow[i] = make_float4(0.f, 0.f, 0.f, 0.f);
        return;
    }
    const int* wsb = g_wstart + (size_t)b * (S + 1);
    int st = wsb[s];
    int en = wsb[s + 1];
    float inv = 1.f / (float)(en - st);
    const float4* ybase = (const float4*)(g_Y + ((size_t)b * S) * D);
    const float4* bc4 = (const float4*)bcomb;

    for (int i = threadIdx.x; i < n4; i += blockDim.x) {
        float4 acc = make_float4(0.f, 0.f, 0.f, 0.f);
        for (int t = st; t < en; t++) {
            float4 v = ybase[(size_t)t * n4 + i];
            acc.x += v.x; acc.y += v.y; acc.z += v.z; acc.w += v.w;
        }
        float4 bb = bc4[i];
        orow[i] = make_float4(acc.x * inv + bb.x, acc.y * inv + bb.y,
                              acc.z * inv + bb.z, acc.w * inv + bb.w);
    }
}

// ---------------------------------------------------------------------------
extern "C" void kernel_launch(void* const* d_in, const int* in_sizes, int n_in,
                              void* d_out, int out_size)
{
    const float* frame  = (const float*)d_in[0];
    const float* wscore = (const float*)d_in[1];
    const float* bscore = (const float*)d_in[2];
    const float* wcomb  = (const float*)d_in[3];
    const float* bcomb  = (const float*)d_in[4];
    float* out = (float*)d_out;

    int D   = in_sizes[1] / 2;          // w_score is [2D, 1]
    long total = in_sizes[0];           // B*S*D
    int BS  = (int)(total / D);

    // Derive B from the n_words tail in the output, fallback to divisors.
    int B = out_size - (int)total;
    if (B <= 0 || B > MAX_B || (BS % B) != 0) {
        B = 16;
        while (B > 1 && (BS % B) != 0) B >>= 1;
    }
    int S = BS / B;
    float* tail = (out_size == (int)total + B) ? (out + total) : nullptr;

    // 1) per-frame score dots (one warp per frame)
    {
        int warps_per_block = 8;
        int blocks = (BS + warps_per_block - 1) / warps_per_block;
        k_score<<<blocks, warps_per_block * 32>>>(frame, wscore, D, BS);
    }
    // 2) per-batch scan -> word boundaries (+ n_words tail)
    k_scan<<<B, 256>>>(bscore, S, tail);
    // 3) dense Y = frame @ w_comb (independent of scan)
    {
        dim3 grid(D / BN, BS / BM);
        k_gemm<<<grid, 256>>>(frame, wcomb, BS, D, D);
    }
    // 4) segment-average + bias + zero-fill
    {
        dim3 grid(S, B);
        k_avg<<<grid, 128>>>(bcomb, out, S, D);
    }
}

// round 4
// speedup vs baseline: 2.3599x; 2.3599x over previous
#include <cuda_runtime.h>
#include <cuda_bf16.h>
#include <cstdint>

// ===========================================================================
// WordSpeechContinuousFusion  (B=16, S=2048, D=512)
//
//   k_score     : p[i]=frame_i.w1, q[i]=frame_i.w2          (1 frame read)
//   k_scan      : per-batch scan of start flags -> word_start[], n_words[]
//   k_segmean   : M[b,s] = mean(frame[st:en])   (valid words only)
//   k_tgemm_mma : out = M @ w_comb (+bias, mask) via mma.sync tf32
//                 (legacy tensor path: this toolchain targets plain sm_100,
//                  no tcgen05)
//
// Fallback SIMT path retained for D != 512.
// ===========================================================================

#define MAX_BS   65536
#define MAX_B    4096
#define Y_ELEMS  ((size_t)1 << 24)   // 32768*512 fp32

__device__ float g_p[MAX_BS];
__device__ float g_q[MAX_BS];
__device__ float g_Y[Y_ELEMS];       // tensor path: segmean M ; fallback: Y
__device__ int   g_wstart[MAX_BS + MAX_B + 1];
__device__ int   g_nw[MAX_B];

// ---------------------------------------------------------------------------
__device__ __forceinline__ uint32_t smem_u32(const void* p) {
    uint32_t a;
    asm("{ .reg .u64 t; cvta.to.shared.u64 t, %1; cvt.u32.u64 %0, t; }"
        : "=r"(a) : "l"(p));
    return a;
}
__device__ __forceinline__ void cp16(uint32_t dst, const void* src) {
    asm volatile("cp.async.cg.shared.global [%0], [%1], 16;" :: "r"(dst), "l"(src));
}
__device__ __forceinline__ uint32_t f2tf32(float f) {
    uint32_t u;
    asm("cvt.rna.tf32.f32 %0, %1;" : "=r"(u) : "f"(f));
    return u;
}
__device__ __forceinline__ void mma_tf32(float* c, const uint32_t* a, const uint32_t* b) {
    asm volatile(
        "mma.sync.aligned.m16n8k8.row.col.f32.tf32.tf32.f32 "
        "{%0,%1,%2,%3}, {%4,%5,%6,%7}, {%8,%9}, {%0,%1,%2,%3};"
        : "+f"(c[0]), "+f"(c[1]), "+f"(c[2]), "+f"(c[3])
        : "r"(a[0]), "r"(a[1]), "r"(a[2]), "r"(a[3]), "r"(b[0]), "r"(b[1]));
}

// ---------------------------------------------------------------------------
// Kernel 1: per-frame dots with the two halves of w_score (warp per frame).
// ---------------------------------------------------------------------------
__global__ void k_score(const float* __restrict__ x,
                        const float* __restrict__ wscore,
                        int D, int BS)
{
    int gw   = (blockIdx.x * blockDim.x + threadIdx.x) >> 5;
    int lane = threadIdx.x & 31;
    if (gw >= BS) return;

    const float4* f  = (const float4*)(x + (size_t)gw * D);
    const float4* w1 = (const float4*)(wscore);
    const float4* w2 = (const float4*)(wscore + D);
    int n4 = D >> 2;

    float a = 0.f, b = 0.f;
    for (int i = lane; i < n4; i += 32) {
        float4 xv = f[i];
        float4 w1v = w1[i];
        float4 w2v = w2[i];
        a += xv.x * w1v.x + xv.y * w1v.y + xv.z * w1v.z + xv.w * w1v.w;
        b += xv.x * w2v.x + xv.y * w2v.y + xv.z * w2v.z + xv.w * w2v.w;
    }
    #pragma unroll
    for (int o = 16; o; o >>= 1) {
        a += __shfl_xor_sync(0xffffffffu, a, o);
        b += __shfl_xor_sync(0xffffffffu, b, o);
    }
    if (lane == 0) { g_p[gw] = a; g_q[gw] = b; }
}

// ---------------------------------------------------------------------------
// Kernel 2: per-batch scan of start flags -> word boundaries + n_words.
// ---------------------------------------------------------------------------
__global__ void k_scan(const float* __restrict__ bscore_p,
                       int S, float* __restrict__ tail)
{
    const int T = 256;
    int b   = blockIdx.x;
    int tid = threadIdx.x;
    int chunk = (S + T - 1) / T;
    if (chunk > 16) chunk = 16;

    const float* pb = g_p + (size_t)b * S;
    const float* qb = g_q + (size_t)b * S;
    float bsc = *bscore_p;

    int local[16];
    int sum = 0;
    for (int i = 0; i < chunk; i++) {
        int t = tid * chunk + i;
        int st = 0;
        if (t > 0 && t < S) {
            float sc = pb[t - 1] + qb[t] + bsc;
            st = (sc > 0.5f) ? 0 : 1;
        }
        sum += st;
        local[i] = sum;
    }

    int lane = tid & 31, w = tid >> 5;
    int v = sum;
    #pragma unroll
    for (int o = 1; o < 32; o <<= 1) {
        int n = __shfl_up_sync(0xffffffffu, v, o);
        if (lane >= o) v += n;
    }
    __shared__ int wsum[8];
    __shared__ int woff[9];
    if (lane == 31) wsum[w] = v;
    __syncthreads();
    if (tid == 0) {
        int acc = 0;
        for (int i = 0; i < 8; i++) { woff[i] = acc; acc += wsum[i]; }
        woff[8] = acc;
    }
    __syncthreads();

    int excl = woff[w] + (v - sum);
    int* wsb = g_wstart + (size_t)b * (S + 1);
    for (int i = 0; i < chunk; i++) {
        int t = tid * chunk + i;
        if (t < S) {
            int stflag = local[i] - (i ? local[i - 1] : 0);
            int seg = excl + local[i];
            if (t == 0 || stflag) wsb[seg] = t;
        }
    }
    if (tid == 0) {
        int nw = woff[8] + 1;
        wsb[nw] = S;
        g_nw[b] = nw;
        if (tail) tail[b] = (float)nw;
    }
}

// ---------------------------------------------------------------------------
// Kernel 3: segment mean of frames -> g_Y (valid words only).
// ---------------------------------------------------------------------------
__global__ void k_segmean(const float* __restrict__ frame, int S, int D)
{
    int b = blockIdx.y, s = blockIdx.x;
    if (s >= g_nw[b]) return;
    const int* wsb = g_wstart + (size_t)b * (S + 1);
    int st = wsb[s], en = wsb[s + 1];
    float inv = 1.f / (float)(en - st);
    int n4 = D >> 2;
    const float4* fb = (const float4*)(frame + ((size_t)b * S) * D);
    float4* mr = (float4*)(g_Y + ((size_t)b * S + s) * D);
    for (int i = threadIdx.x; i < n4; i += blockDim.x) {
        float4 acc = make_float4(0.f, 0.f, 0.f, 0.f);
        for (int t = st; t < en; t++) {
            float4 v = fb[(size_t)t * n4 + i];
            acc.x += v.x; acc.y += v.y; acc.z += v.z; acc.w += v.w;
        }
        mr[i] = make_float4(acc.x * inv, acc.y * inv, acc.z * inv, acc.w * inv);
    }
}

// ---------------------------------------------------------------------------
// Kernel 4: mma.sync tf32 GEMM.  out[BS,512] = M[BS,512] @ W[512,512]
// (+bias, zero rows with s >= n_words[b]).
// Block tile 128x128x32, 8 warps of 64x32, double-buffered cp.async.
// Smem: A [128][36] fl (stride 144B), B [32][136] fl (stride 544B).
// Both strides 16B-aligned (cp.async) and conflict-free for fragment LDS.
// ---------------------------------------------------------------------------
#define MM_ASTRIDE 36
#define MM_BSTRIDE 136
#define MM_ABYTES  (128 * MM_ASTRIDE * 4)       // 18432
#define MM_BBYTES  (32 * MM_BSTRIDE * 4)        // 17408
#define MM_STAGE   (MM_ABYTES + MM_BBYTES)      // 35840
#define MM_SMEM    (2 * MM_STAGE)               // 71680

__device__ __forceinline__ void mm_load(uint32_t base, int stage,
                                        const float* __restrict__ Ag,
                                        const float* __restrict__ W,
                                        long m0, int n0, int k0, int tid)
{
    uint32_t a_s = base + (uint32_t)stage * MM_STAGE;
    uint32_t b_s = a_s + MM_ABYTES;
    #pragma unroll
    for (int j = 0; j < 4; j++) {                // A: 128 rows x 32 fl
        int L = tid + 256 * j;
        int row = L >> 3, seg = L & 7;
        cp16(a_s + (uint32_t)row * (MM_ASTRIDE * 4) + (uint32_t)seg * 16,
             Ag + (m0 + row) * 512 + k0 + seg * 4);
    }
    #pragma unroll
    for (int j = 0; j < 4; j++) {                // B: 32 rows x 128 fl
        int L = tid + 256 * j;
        int row = L >> 5, seg = L & 31;
        cp16(b_s + (uint32_t)row * (MM_BSTRIDE * 4) + (uint32_t)seg * 16,
             W + (size_t)(k0 + row) * 512 + n0 + seg * 4);
    }
    asm volatile("cp.async.commit_group;" ::: "memory");
}

__global__ __launch_bounds__(256, 2)
void k_tgemm_mma(const float* __restrict__ W,
                 const float* __restrict__ bcomb,
                 float* __restrict__ out, int S)
{
    extern __shared__ char smem[];
    uint32_t base = smem_u32(smem);
    const float* Ag = g_Y;

    int tid  = threadIdx.x;
    int lane = tid & 31;
    int wid  = tid >> 5;
    int wm   = wid & 1;          // 0/1 -> 64-row half
    int wn   = wid >> 1;         // 0..3 -> 32-col quarter
    int g    = lane >> 2;        // groupID
    int t    = lane & 3;         // threadID_in_group

    long m0 = (long)blockIdx.y * 128;
    int  n0 = blockIdx.x * 128;

    float c[4][4][4];
    #pragma unroll
    for (int i = 0; i < 4; i++)
        #pragma unroll
        for (int j = 0; j < 4; j++)
            #pragma unroll
            for (int r = 0; r < 4; r++) c[i][j][r] = 0.f;

    mm_load(base, 0, Ag, W, m0, n0, 0, tid);

    const float* As;
    const float* Bs;
    #pragma unroll 1
    for (int ch = 0; ch < 16; ch++) {
        if (ch + 1 < 16) {
            mm_load(base, (ch + 1) & 1, Ag, W, m0, n0, (ch + 1) * 32, tid);
            asm volatile("cp.async.wait_group 1;" ::: "memory");
        } else {
            asm volatile("cp.async.wait_group 0;" ::: "memory");
        }
        __syncthreads();

        {
            uint32_t a_s = base + (uint32_t)(ch & 1) * MM_STAGE;
            As = (const float*)(smem + (a_s - base));
            Bs = (const float*)(smem + (a_s - base) + MM_ABYTES);
        }

        #pragma unroll
        for (int kk = 0; kk < 32; kk += 8) {
            uint32_t af[4][4];
            #pragma unroll
            for (int mt = 0; mt < 4; mt++) {
                int r0 = wm * 64 + mt * 16 + g;
                const float* ap = As + (size_t)r0 * MM_ASTRIDE + kk + t;
                af[mt][0] = f2tf32(ap[0]);
                af[mt][1] = f2tf32(ap[8 * MM_ASTRIDE]);
                af[mt][2] = f2tf32(ap[4]);
                af[mt][3] = f2tf32(ap[8 * MM_ASTRIDE + 4]);
            }
            uint32_t bf[4][2];
            #pragma unroll
            for (int nt = 0; nt < 4; nt++) {
                int col = wn * 32 + nt * 8 + g;
                const float* bp = Bs + (size_t)(kk + t) * MM_BSTRIDE + col;
                bf[nt][0] = f2tf32(bp[0]);
                bf[nt][1] = f2tf32(bp[4 * MM_BSTRIDE]);
            }
            #pragma unroll
            for (int mt = 0; mt < 4; mt++)
                #pragma unroll
                for (int nt = 0; nt < 4; nt++)
                    mma_tf32(c[mt][nt], af[mt], bf[nt]);
        }
        __syncthreads();
    }

    // epilogue: bias + validity mask, float2 stores
    #pragma unroll
    for (int mt = 0; mt < 4; mt++) {
        #pragma unroll
        for (int half = 0; half < 2; half++) {
            long grow = m0 + wm * 64 + mt * 16 + g + half * 8;
            int b = (int)(grow / S);
            int s = (int)(grow - (long)b * S);
            bool valid = s < g_nw[b];
            float* orow = out + grow * 512 + n0;
            #pragma unroll
            for (int nt = 0; nt < 4; nt++) {
                int col = wn * 32 + nt * 8 + t * 2;
                float2 v;
                if (valid) {
                    v.x = c[mt][nt][half * 2 + 0] + bcomb[n0 + col];
                    v.y = c[mt][nt][half * 2 + 1] + bcomb[n0 + col + 1];
                } else {
                    v.x = 0.f; v.y = 0.f;
                }
                *(float2*)(orow + col) = v;
            }
        }
    }
}

// ---------------------------------------------------------------------------
// Fallback SIMT path (D != 512): fp32 SGEMM + segment-average.
// ---------------------------------------------------------------------------
#define BM 128
#define BN 128
#define BK 8
__global__ __launch_bounds__(256, 2)
void k_gemm(const float* __restrict__ A, const float* __restrict__ Wm,
            int M, int N, int K)
{
    __shared__ float As[2][BK][BM];
    __shared__ float Bs[2][BK][BN];
    int bx = blockIdx.x, by = blockIdx.y;
    int tid = threadIdx.x;
    int tx = tid & 15, ty = tid >> 4;
    int arow = tid >> 1, acol = (tid & 1) * 4;
    int brow = tid >> 5, bcol = (tid & 31) * 4;
    const float* Ap = A + ((size_t)(by * BM + arow)) * K + acol;
    const float* Bp = Wm + (size_t)brow * N + bx * BN + bcol;

    float acc[8][8];
    #pragma unroll
    for (int i = 0; i < 8; i++)
        #pragma unroll
        for (int j = 0; j < 8; j++) acc[i][j] = 0.f;

    float4 a4 = *(const float4*)Ap;
    float4 b4 = *(const float4*)Bp;
    As[0][acol + 0][arow] = a4.x; As[0][acol + 1][arow] = a4.y;
    As[0][acol + 2][arow] = a4.z; As[0][acol + 3][arow] = a4.w;
    *(float4*)&Bs[0][brow][bcol] = b4;
    __syncthreads();

    int buf = 0;
    for (int k0 = 0; k0 < K; k0 += BK) {
        bool more = (k0 + BK) < K;
        float4 na, nb;
        if (more) {
            na = *(const float4*)(Ap + (k0 + BK));
            nb = *(const float4*)(Bp + (size_t)(k0 + BK) * N);
        }
        #pragma unroll
        for (int k = 0; k < BK; k++) {
            float ra[8], rb[8];
            *(float4*)(ra + 0) = *(float4*)&As[buf][k][ty * 4];
            *(float4*)(ra + 4) = *(float4*)&As[buf][k][64 + ty * 4];
            *(float4*)(rb + 0) = *(float4*)&Bs[buf][k][tx * 4];
            *(float4*)(rb + 4) = *(float4*)&Bs[buf][k][64 + tx * 4];
            #pragma unroll
            for (int i = 0; i < 8; i++)
                #pragma unroll
                for (int j = 0; j < 8; j++)
                    acc[i][j] = fmaf(ra[i], rb[j], acc[i][j]);
        }
        if (more) {
            int nxt = buf ^ 1;
            As[nxt][acol + 0][arow] = na.x; As[nxt][acol + 1][arow] = na.y;
            As[nxt][acol + 2][arow] = na.z; As[nxt][acol + 3][arow] = na.w;
            *(float4*)&Bs[nxt][brow][bcol] = nb;
            __syncthreads();
            buf = nxt;
        }
    }
    #pragma unroll
    for (int i = 0; i < 8; i++) {
        int r = by * BM + ((i < 4) ? (ty * 4 + i) : (64 + ty * 4 + i - 4));
        float* crow = g_Y + (size_t)r * N + bx * BN;
        *(float4*)(crow + tx * 4)      = make_float4(acc[i][0], acc[i][1], acc[i][2], acc[i][3]);
        *(float4*)(crow + 64 + tx * 4) = make_float4(acc[i][4], acc[i][5], acc[i][6], acc[i][7]);
    }
}

__global__ void k_avg(const float* __restrict__ bcomb,
                      float* __restrict__ out, int S, int D)
{
    int b = blockIdx.y, s = blockIdx.x;
    int n4 = D >> 2;
    float4* orow = (float4*)(out + ((size_t)b * S + s) * D);
    int nw = g_nw[b];
    if (s >= nw) {
        for (int i = threadIdx.x; i < n4; i += blockDim.x)
            orow[i] = make_float4(0.f, 0.f, 0.f, 0.f);
        return;
    }
    const int* wsb = g_wstart + (size_t)b * (S + 1);
    int st = wsb[s], en = wsb[s + 1];
    float inv = 1.f / (float)(en - st);
    const float4* ybase = (const float4*)(g_Y + ((size_t)b * S) * D);
    const float4* bc4 = (const float4*)bcomb;
    for (int i = threadIdx.x; i < n4; i += blockDim.x) {
        float4 acc = make_float4(0.f, 0.f, 0.f, 0.f);
        for (int tt = st; tt < en; tt++) {
            float4 v = ybase[(size_t)tt * n4 + i];
            acc.x += v.x; acc.y += v.y; acc.z += v.z; acc.w += v.w;
        }
        float4 bb = bc4[i];
        orow[i] = make_float4(acc.x * inv + bb.x, acc.y * inv + bb.y,
                              acc.z * inv + bb.z, acc.w * inv + bb.w);
    }
}

// ---------------------------------------------------------------------------
extern "C" void kernel_launch(void* const* d_in, const int* in_sizes, int n_in,
                              void* d_out, int out_size)
{
    const float* frame  = (const float*)d_in[0];
    const float* wscore = (const float*)d_in[1];
    const float* bscore = (const float*)d_in[2];
    const float* wcomb  = (const float*)d_in[3];
    const float* bcomb  = (const float*)d_in[4];
    float* out = (float*)d_out;

    int D   = in_sizes[1] / 2;
    long total = in_sizes[0];
    int BS  = (int)(total / D);

    int B = out_size - (int)total;
    if (B <= 0 || B > MAX_B || (BS % B) != 0) {
        B = 16;
        while (B > 1 && (BS % B) != 0) B >>= 1;
    }
    int S = BS / B;
    float* tail = (out_size == (int)total + B) ? (out + total) : nullptr;

    // 1) per-frame score dots
    {
        int wpb = 8;
        int blocks = (BS + wpb - 1) / wpb;
        k_score<<<blocks, wpb * 32>>>(frame, wscore, D, BS);
    }
    // 2) per-batch scan
    k_scan<<<B, 256>>>(bscore, S, tail);

    if (D == 512 && (BS % 128) == 0) {
        // --- tensor path (mma.sync tf32) ---
        {
            dim3 grid(S, B);
            k_segmean<<<grid, 128>>>(frame, S, D);
        }
        static int smem_set = 0;
        if (!smem_set) {
            cudaFuncSetAttribute(k_tgemm_mma,
                                 cudaFuncAttributeMaxDynamicSharedMemorySize, MM_SMEM);
            smem_set = 1;
        }
        dim3 grid(512 / 128, BS / 128);
        k_tgemm_mma<<<grid, 256, MM_SMEM>>>(wcomb, bcomb, out, S);
    } else {
        // --- fallback SIMT path ---
        dim3 grid(D / BN, BS / BM);
        k_gemm<<<grid, 256>>>(frame, wcomb, BS, D, D);
        dim3 agrid(S, B);
        k_avg<<<agrid, 128>>>(bcomb, out, S, D);
    }
}

// round 5
// speedup vs baseline: 2.8311x; 1.1997x over previous
#include <cuda_runtime.h>
#include <cuda_bf16.h>
#include <cstdint>

// ===========================================================================
// WordSpeechContinuousFusion  (B=16, S=2048, D=512)
//
//   k_score     : p[i]=frame_i.w1, q[i]=frame_i.w2          (1 frame read)
//   k_scan      : per-batch scan of start flags -> word_start[], n_words[]
//   k_roundw    : Wr = tf32_rna(w_comb)        (hoisted rounding, 1MB)
//   k_segmean   : M[b,s] = tf32_rna(mean(frame[st:en]))   (valid words)
//   k_tgemm_mma : out = M @ Wr (+bias, mask) via mma.sync tf32
//                 - no cvt in inner loop (inputs pre-rounded)
//                 - fully-invalid M-tiles zero-fill + early-exit
//
// Fallback SIMT path retained for D != 512.
// ===========================================================================

#define MAX_BS   65536
#define MAX_B    4096
#define Y_ELEMS  ((size_t)1 << 24)   // 32768*512 fp32

__device__ float g_p[MAX_BS];
__device__ float g_q[MAX_BS];
__device__ float g_Y[Y_ELEMS];       // tensor path: rounded segmean ; fallback: Y
__device__ float g_Wr[512 * 512];    // tf32-rounded w_comb
__device__ int   g_wstart[MAX_BS + MAX_B + 1];
__device__ int   g_nw[MAX_B];

// ---------------------------------------------------------------------------
__device__ __forceinline__ uint32_t smem_u32(const void* p) {
    uint32_t a;
    asm("{ .reg .u64 t; cvta.to.shared.u64 t, %1; cvt.u32.u64 %0, t; }"
        : "=r"(a) : "l"(p));
    return a;
}
__device__ __forceinline__ void cp16(uint32_t dst, const void* src) {
    asm volatile("cp.async.cg.shared.global [%0], [%1], 16;" :: "r"(dst), "l"(src));
}
__device__ __forceinline__ float f2tf32f(float f) {
    uint32_t u;
    asm("cvt.rna.tf32.f32 %0, %1;" : "=r"(u) : "f"(f));
    return __uint_as_float(u);
}
__device__ __forceinline__ void mma_tf32(float* c, const uint32_t* a, const uint32_t* b) {
    asm volatile(
        "mma.sync.aligned.m16n8k8.row.col.f32.tf32.tf32.f32 "
        "{%0,%1,%2,%3}, {%4,%5,%6,%7}, {%8,%9}, {%0,%1,%2,%3};"
        : "+f"(c[0]), "+f"(c[1]), "+f"(c[2]), "+f"(c[3])
        : "r"(a[0]), "r"(a[1]), "r"(a[2]), "r"(a[3]), "r"(b[0]), "r"(b[1]));
}

// ---------------------------------------------------------------------------
// Kernel 1: per-frame dots with the two halves of w_score (warp per frame).
// ---------------------------------------------------------------------------
__global__ void k_score(const float* __restrict__ x,
                        const float* __restrict__ wscore,
                        int D, int BS)
{
    int gw   = (blockIdx.x * blockDim.x + threadIdx.x) >> 5;
    int lane = threadIdx.x & 31;
    if (gw >= BS) return;

    const float4* f  = (const float4*)(x + (size_t)gw * D);
    const float4* w1 = (const float4*)(wscore);
    const float4* w2 = (const float4*)(wscore + D);
    int n4 = D >> 2;

    float a = 0.f, b = 0.f;
    for (int i = lane; i < n4; i += 32) {
        float4 xv = f[i];
        float4 w1v = w1[i];
        float4 w2v = w2[i];
        a += xv.x * w1v.x + xv.y * w1v.y + xv.z * w1v.z + xv.w * w1v.w;
        b += xv.x * w2v.x + xv.y * w2v.y + xv.z * w2v.z + xv.w * w2v.w;
    }
    #pragma unroll
    for (int o = 16; o; o >>= 1) {
        a += __shfl_xor_sync(0xffffffffu, a, o);
        b += __shfl_xor_sync(0xffffffffu, b, o);
    }
    if (lane == 0) { g_p[gw] = a; g_q[gw] = b; }
}

// ---------------------------------------------------------------------------
// Kernel 2: per-batch scan of start flags -> word boundaries + n_words.
// ---------------------------------------------------------------------------
__global__ void k_scan(const float* __restrict__ bscore_p,
                       int S, float* __restrict__ tail)
{
    const int T = 256;
    int b   = blockIdx.x;
    int tid = threadIdx.x;
    int chunk = (S + T - 1) / T;
    if (chunk > 16) chunk = 16;

    const float* pb = g_p + (size_t)b * S;
    const float* qb = g_q + (size_t)b * S;
    float bsc = *bscore_p;

    int local[16];
    int sum = 0;
    for (int i = 0; i < chunk; i++) {
        int t = tid * chunk + i;
        int st = 0;
        if (t > 0 && t < S) {
            float sc = pb[t - 1] + qb[t] + bsc;
            st = (sc > 0.5f) ? 0 : 1;
        }
        sum += st;
        local[i] = sum;
    }

    int lane = tid & 31, w = tid >> 5;
    int v = sum;
    #pragma unroll
    for (int o = 1; o < 32; o <<= 1) {
        int n = __shfl_up_sync(0xffffffffu, v, o);
        if (lane >= o) v += n;
    }
    __shared__ int wsum[8];
    __shared__ int woff[9];
    if (lane == 31) wsum[w] = v;
    __syncthreads();
    if (tid == 0) {
        int acc = 0;
        for (int i = 0; i < 8; i++) { woff[i] = acc; acc += wsum[i]; }
        woff[8] = acc;
    }
    __syncthreads();

    int excl = woff[w] + (v - sum);
    int* wsb = g_wstart + (size_t)b * (S + 1);
    for (int i = 0; i < chunk; i++) {
        int t = tid * chunk + i;
        if (t < S) {
            int stflag = local[i] - (i ? local[i - 1] : 0);
            int seg = excl + local[i];
            if (t == 0 || stflag) wsb[seg] = t;
        }
    }
    if (tid == 0) {
        int nw = woff[8] + 1;
        wsb[nw] = S;
        g_nw[b] = nw;
        if (tail) tail[b] = (float)nw;
    }
}

// ---------------------------------------------------------------------------
// Kernel W: pre-round w_comb to tf32 (rna).
// ---------------------------------------------------------------------------
__global__ void k_roundw(const float* __restrict__ w, int n)
{
    int i = (blockIdx.x * blockDim.x + threadIdx.x) * 4;
    if (i + 3 < n) {
        float4 v = *(const float4*)(w + i);
        v.x = f2tf32f(v.x); v.y = f2tf32f(v.y);
        v.z = f2tf32f(v.z); v.w = f2tf32f(v.w);
        *(float4*)(g_Wr + i) = v;
    }
}

// ---------------------------------------------------------------------------
// Kernel 3: segment mean of frames -> g_Y, pre-rounded to tf32.
// ---------------------------------------------------------------------------
__global__ void k_segmean(const float* __restrict__ frame, int S, int D)
{
    int b = blockIdx.y, s = blockIdx.x;
    if (s >= g_nw[b]) return;
    const int* wsb = g_wstart + (size_t)b * (S + 1);
    int st = wsb[s], en = wsb[s + 1];
    float inv = 1.f / (float)(en - st);
    int n4 = D >> 2;
    const float4* fb = (const float4*)(frame + ((size_t)b * S) * D);
    float4* mr = (float4*)(g_Y + ((size_t)b * S + s) * D);
    for (int i = threadIdx.x; i < n4; i += blockDim.x) {
        float4 acc = make_float4(0.f, 0.f, 0.f, 0.f);
        for (int t = st; t < en; t++) {
            float4 v = fb[(size_t)t * n4 + i];
            acc.x += v.x; acc.y += v.y; acc.z += v.z; acc.w += v.w;
        }
        mr[i] = make_float4(f2tf32f(acc.x * inv), f2tf32f(acc.y * inv),
                            f2tf32f(acc.z * inv), f2tf32f(acc.w * inv));
    }
}

// ---------------------------------------------------------------------------
// Kernel 4: mma.sync tf32 GEMM.  out[BS,512] = M[BS,512] @ Wr[512,512]
// (+bias, zero rows with s >= n_words[b]).  Inputs pre-rounded -> no cvt.
// Fully-invalid M-tiles: zero-fill + early exit.
// ---------------------------------------------------------------------------
#define MM_ASTRIDE 36
#define MM_BSTRIDE 136
#define MM_ABYTES  (128 * MM_ASTRIDE * 4)       // 18432
#define MM_BBYTES  (32 * MM_BSTRIDE * 4)        // 17408
#define MM_STAGE   (MM_ABYTES + MM_BBYTES)      // 35840
#define MM_SMEM    (2 * MM_STAGE)               // 71680

__device__ __forceinline__ void mm_load(uint32_t base, int stage,
                                        const float* __restrict__ Ag,
                                        const float* __restrict__ Wg,
                                        long m0, int n0, int k0, int tid)
{
    uint32_t a_s = base + (uint32_t)stage * MM_STAGE;
    uint32_t b_s = a_s + MM_ABYTES;
    #pragma unroll
    for (int j = 0; j < 4; j++) {                // A: 128 rows x 32 fl
        int L = tid + 256 * j;
        int row = L >> 3, seg = L & 7;
        cp16(a_s + (uint32_t)row * (MM_ASTRIDE * 4) + (uint32_t)seg * 16,
             Ag + (m0 + row) * 512 + k0 + seg * 4);
    }
    #pragma unroll
    for (int j = 0; j < 4; j++) {                // B: 32 rows x 128 fl
        int L = tid + 256 * j;
        int row = L >> 5, seg = L & 31;
        cp16(b_s + (uint32_t)row * (MM_BSTRIDE * 4) + (uint32_t)seg * 16,
             Wg + (size_t)(k0 + row) * 512 + n0 + seg * 4);
    }
    asm volatile("cp.async.commit_group;" ::: "memory");
}

__global__ __launch_bounds__(256, 2)
void k_tgemm_mma(const float* __restrict__ bcomb,
                 float* __restrict__ out, int S)
{
    extern __shared__ char smem[];
    uint32_t base = smem_u32(smem);
    const float* Ag = g_Y;
    const float* Wg = g_Wr;

    int tid  = threadIdx.x;
    long m0 = (long)blockIdx.y * 128;
    int  n0 = blockIdx.x * 128;

    // ---- fully-invalid tile: zero-fill our column strip and exit ----
    {
        int b0 = (int)(m0 / S);
        int s0 = (int)(m0 - (long)b0 * S);
        if (s0 + 128 <= S && s0 >= g_nw[b0]) {
            // 128 rows x 128 cols; 256 threads -> 64 floats each
            float4 z = make_float4(0.f, 0.f, 0.f, 0.f);
            #pragma unroll
            for (int j = 0; j < 16; j++) {
                int L = tid + 256 * j;              // 4096 float4 slots
                int row = L >> 5, seg = L & 31;
                *(float4*)(out + (m0 + row) * 512 + n0 + seg * 4) = z;
            }
            return;
        }
    }

    int lane = tid & 31;
    int wid  = tid >> 5;
    int wm   = wid & 1;          // 0/1 -> 64-row half
    int wn   = wid >> 1;         // 0..3 -> 32-col quarter
    int g    = lane >> 2;        // groupID
    int t    = lane & 3;         // threadID_in_group

    float c[4][4][4];
    #pragma unroll
    for (int i = 0; i < 4; i++)
        #pragma unroll
        for (int j = 0; j < 4; j++)
            #pragma unroll
            for (int r = 0; r < 4; r++) c[i][j][r] = 0.f;

    mm_load(base, 0, Ag, Wg, m0, n0, 0, tid);

    #pragma unroll 1
    for (int ch = 0; ch < 16; ch++) {
        if (ch + 1 < 16) {
            mm_load(base, (ch + 1) & 1, Ag, Wg, m0, n0, (ch + 1) * 32, tid);
            asm volatile("cp.async.wait_group 1;" ::: "memory");
        } else {
            asm volatile("cp.async.wait_group 0;" ::: "memory");
        }
        __syncthreads();

        const float* As = (const float*)(smem + (size_t)(ch & 1) * MM_STAGE);
        const float* Bs = (const float*)(smem + (size_t)(ch & 1) * MM_STAGE + MM_ABYTES);

        #pragma unroll
        for (int kk = 0; kk < 32; kk += 8) {
            uint32_t af[4][4];
            #pragma unroll
            for (int mt = 0; mt < 4; mt++) {
                int r0 = wm * 64 + mt * 16 + g;
                const float* ap = As + (size_t)r0 * MM_ASTRIDE + kk + t;
                af[mt][0] = __float_as_uint(ap[0]);
                af[mt][1] = __float_as_uint(ap[8 * MM_ASTRIDE]);
                af[mt][2] = __float_as_uint(ap[4]);
                af[mt][3] = __float_as_uint(ap[8 * MM_ASTRIDE + 4]);
            }
            uint32_t bf[4][2];
            #pragma unroll
            for (int nt = 0; nt < 4; nt++) {
                int col = wn * 32 + nt * 8 + g;
                const float* bp = Bs + (size_t)(kk + t) * MM_BSTRIDE + col;
                bf[nt][0] = __float_as_uint(bp[0]);
                bf[nt][1] = __float_as_uint(bp[4 * MM_BSTRIDE]);
            }
            #pragma unroll
            for (int mt = 0; mt < 4; mt++)
                #pragma unroll
                for (int nt = 0; nt < 4; nt++)
                    mma_tf32(c[mt][nt], af[mt], bf[nt]);
        }
        __syncthreads();
    }

    // epilogue: bias + validity mask, float2 stores
    #pragma unroll
    for (int mt = 0; mt < 4; mt++) {
        #pragma unroll
        for (int half = 0; half < 2; half++) {
            long grow = m0 + wm * 64 + mt * 16 + g + half * 8;
            int b = (int)(grow / S);
            int s = (int)(grow - (long)b * S);
            bool valid = s < g_nw[b];
            float* orow = out + grow * 512 + n0;
            #pragma unroll
            for (int nt = 0; nt < 4; nt++) {
                int col = wn * 32 + nt * 8 + t * 2;
                float2 v;
                if (valid) {
                    v.x = c[mt][nt][half * 2 + 0] + bcomb[n0 + col];
                    v.y = c[mt][nt][half * 2 + 1] + bcomb[n0 + col + 1];
                } else {
                    v.x = 0.f; v.y = 0.f;
                }
                *(float2*)(orow + col) = v;
            }
        }
    }
}

// ---------------------------------------------------------------------------
// Fallback SIMT path (D != 512): fp32 SGEMM + segment-average.
// ---------------------------------------------------------------------------
#define BM 128
#define BN 128
#define BK 8
__global__ __launch_bounds__(256, 2)
void k_gemm(const float* __restrict__ A, const float* __restrict__ Wm,
            int M, int N, int K)
{
    __shared__ float As[2][BK][BM];
    __shared__ float Bs[2][BK][BN];
    int bx = blockIdx.x, by = blockIdx.y;
    int tid = threadIdx.x;
    int tx = tid & 15, ty = tid >> 4;
    int arow = tid >> 1, acol = (tid & 1) * 4;
    int brow = tid >> 5, bcol = (tid & 31) * 4;
    const float* Ap = A + ((size_t)(by * BM + arow)) * K + acol;
    const float* Bp = Wm + (size_t)brow * N + bx * BN + bcol;

    float acc[8][8];
    #pragma unroll
    for (int i = 0; i < 8; i++)
        #pragma unroll
        for (int j = 0; j < 8; j++) acc[i][j] = 0.f;

    float4 a4 = *(const float4*)Ap;
    float4 b4 = *(const float4*)Bp;
    As[0][acol + 0][arow] = a4.x; As[0][acol + 1][arow] = a4.y;
    As[0][acol + 2][arow] = a4.z; As[0][acol + 3][arow] = a4.w;
    *(float4*)&Bs[0][brow][bcol] = b4;
    __syncthreads();

    int buf = 0;
    for (int k0 = 0; k0 < K; k0 += BK) {
        bool more = (k0 + BK) < K;
        float4 na, nb;
        if (more) {
            na = *(const float4*)(Ap + (k0 + BK));
            nb = *(const float4*)(Bp + (size_t)(k0 + BK) * N);
        }
        #pragma unroll
        for (int k = 0; k < BK; k++) {
            float ra[8], rb[8];
            *(float4*)(ra + 0) = *(float4*)&As[buf][k][ty * 4];
            *(float4*)(ra + 4) = *(float4*)&As[buf][k][64 + ty * 4];
            *(float4*)(rb + 0) = *(float4*)&Bs[buf][k][tx * 4];
            *(float4*)(rb + 4) = *(float4*)&Bs[buf][k][64 + tx * 4];
            #pragma unroll
            for (int i = 0; i < 8; i++)
                #pragma unroll
                for (int j = 0; j < 8; j++)
                    acc[i][j] = fmaf(ra[i], rb[j], acc[i][j]);
        }
        if (more) {
            int nxt = buf ^ 1;
            As[nxt][acol + 0][arow] = na.x; As[nxt][acol + 1][arow] = na.y;
            As[nxt][acol + 2][arow] = na.z; As[nxt][acol + 3][arow] = na.w;
            *(float4*)&Bs[nxt][brow][bcol] = nb;
            __syncthreads();
            buf = nxt;
        }
    }
    #pragma unroll
    for (int i = 0; i < 8; i++) {
        int r = by * BM + ((i < 4) ? (ty * 4 + i) : (64 + ty * 4 + i - 4));
        float* crow = g_Y + (size_t)r * N + bx * BN;
        *(float4*)(crow + tx * 4)      = make_float4(acc[i][0], acc[i][1], acc[i][2], acc[i][3]);
        *(float4*)(crow + 64 + tx * 4) = make_float4(acc[i][4], acc[i][5], acc[i][6], acc[i][7]);
    }
}

__global__ void k_avg(const float* __restrict__ bcomb,
                      float* __restrict__ out, int S, int D)
{
    int b = blockIdx.y, s = blockIdx.x;
    int n4 = D >> 2;
    float4* orow = (float4*)(out + ((size_t)b * S + s) * D);
    int nw = g_nw[b];
    if (s >= nw) {
        for (int i = threadIdx.x; i < n4; i += blockDim.x)
            orow[i] = make_float4(0.f, 0.f, 0.f, 0.f);
        return;
    }
    const int* wsb = g_wstart + (size_t)b * (S + 1);
    int st = wsb[s], en = wsb[s + 1];
    float inv = 1.f / (float)(en - st);
    const float4* ybase = (const float4*)(g_Y + ((size_t)b * S) * D);
    const float4* bc4 = (const float4*)bcomb;
    for (int i = threadIdx.x; i < n4; i += blockDim.x) {
        float4 acc = make_float4(0.f, 0.f, 0.f, 0.f);
        for (int tt = st; tt < en; tt++) {
            float4 v = ybase[(size_t)tt * n4 + i];
            acc.x += v.x; acc.y += v.y; acc.z += v.z; acc.w += v.w;
        }
        float4 bb = bc4[i];
        orow[i] = make_float4(acc.x * inv + bb.x, acc.y * inv + bb.y,
                              acc.z * inv + bb.z, acc.w * inv + bb.w);
    }
}

// ---------------------------------------------------------------------------
extern "C" void kernel_launch(void* const* d_in, const int* in_sizes, int n_in,
                              void* d_out, int out_size)
{
    const float* frame  = (const float*)d_in[0];
    const float* wscore = (const float*)d_in[1];
    const float* bscore = (const float*)d_in[2];
    const float* wcomb  = (const float*)d_in[3];
    const float* bcomb  = (const float*)d_in[4];
    float* out = (float*)d_out;

    int D   = in_sizes[1] / 2;
    long total = in_sizes[0];
    int BS  = (int)(total / D);

    int B = out_size - (int)total;
    if (B <= 0 || B > MAX_B || (BS % B) != 0) {
        B = 16;
        while (B > 1 && (BS % B) != 0) B >>= 1;
    }
    int S = BS / B;
    float* tail = (out_size == (int)total + B) ? (out + total) : nullptr;

    // 1) per-frame score dots
    {
        int wpb = 8;
        int blocks = (BS + wpb - 1) / wpb;
        k_score<<<blocks, wpb * 32>>>(frame, wscore, D, BS);
    }
    // 2) per-batch scan
    k_scan<<<B, 256>>>(bscore, S, tail);

    if (D == 512 && (BS % 128) == 0) {
        // --- tensor path (mma.sync tf32, pre-rounded operands) ---
        k_roundw<<<(512 * 512 / 4 + 255) / 256, 256>>>(wcomb, 512 * 512);
        {
            dim3 grid(S, B);
            k_segmean<<<grid, 128>>>(frame, S, D);
        }
        static int smem_set = 0;
        if (!smem_set) {
            cudaFuncSetAttribute(k_tgemm_mma,
                                 cudaFuncAttributeMaxDynamicSharedMemorySize, MM_SMEM);
            smem_set = 1;
        }
        dim3 grid(512 / 128, BS / 128);
        k_tgemm_mma<<<grid, 256, MM_SMEM>>>(bcomb, out, S);
    } else {
        // --- fallback SIMT path ---
        dim3 grid(D / BN, BS / BM);
        k_gemm<<<grid, 256>>>(frame, wcomb, BS, D, D);
        dim3 agrid(S, B);
        k_avg<<<agrid, 128>>>(bcomb, out, S, D);
    }
}

// round 6
// speedup vs baseline: 3.4387x; 1.2146x over previous
#include <cuda_runtime.h>
#include <cuda_bf16.h>
#include <cuda_fp16.h>
#include <cstdint>

// ===========================================================================
// WordSpeechContinuousFusion  (B=16, S=2048, D=512)
//
//   k_score     : p[i]=frame_i.w1, q[i]=frame_i.w2          (1 frame read)
//   k_scan      : per-batch scan of start flags -> word_start[], n_words[]
//   k_prep_w    : Wh = half(w_comb), k-pair-interleaved layout
//   k_segmean   : Mh[b,s] = half(mean(frame[st:en]))   (valid words)
//   k_tgemm_mma : out = Mh @ Wh (+bias, mask) via mma.sync m16n8k16 f16
//                 (fp16 mantissa == tf32 mantissa -> same accuracy, 2x rate)
//
// Fallback SIMT path retained for D != 512.
// ===========================================================================

#define MAX_BS   65536
#define MAX_B    4096
#define Y_ELEMS  ((size_t)1 << 24)   // fallback scratch (fp32)

__device__ float  g_p[MAX_BS];
__device__ float  g_q[MAX_BS];
__device__ float  g_Y[Y_ELEMS];             // fallback path only
__device__ __half g_Mh[(size_t)MAX_BS * 512];   // segmean, half
__device__ __half g_Wh[256 * 1024];             // w_comb, half, k-pair interleaved
__device__ int    g_wstart[MAX_BS + MAX_B + 1];
__device__ int    g_nw[MAX_B];

// ---------------------------------------------------------------------------
__device__ __forceinline__ uint32_t smem_u32(const void* p) {
    uint32_t a;
    asm("{ .reg .u64 t; cvta.to.shared.u64 t, %1; cvt.u32.u64 %0, t; }"
        : "=r"(a) : "l"(p));
    return a;
}
__device__ __forceinline__ void cp16(uint32_t dst, const void* src) {
    asm volatile("cp.async.cg.shared.global [%0], [%1], 16;" :: "r"(dst), "l"(src));
}
__device__ __forceinline__ void mma_f16(float* c, const uint32_t* a, const uint32_t* b) {
    asm volatile(
        "mma.sync.aligned.m16n8k16.row.col.f32.f16.f16.f32 "
        "{%0,%1,%2,%3}, {%4,%5,%6,%7}, {%8,%9}, {%0,%1,%2,%3};"
        : "+f"(c[0]), "+f"(c[1]), "+f"(c[2]), "+f"(c[3])
        : "r"(a[0]), "r"(a[1]), "r"(a[2]), "r"(a[3]), "r"(b[0]), "r"(b[1]));
}

// ---------------------------------------------------------------------------
// Kernel 1: per-frame dots with the two halves of w_score (warp per frame).
// ---------------------------------------------------------------------------
__global__ void k_score(const float* __restrict__ x,
                        const float* __restrict__ wscore,
                        int D, int BS)
{
    int gw   = (blockIdx.x * blockDim.x + threadIdx.x) >> 5;
    int lane = threadIdx.x & 31;
    if (gw >= BS) return;

    const float4* f  = (const float4*)(x + (size_t)gw * D);
    const float4* w1 = (const float4*)(wscore);
    const float4* w2 = (const float4*)(wscore + D);
    int n4 = D >> 2;

    float a = 0.f, b = 0.f;
    for (int i = lane; i < n4; i += 32) {
        float4 xv = f[i];
        float4 w1v = w1[i];
        float4 w2v = w2[i];
        a += xv.x * w1v.x + xv.y * w1v.y + xv.z * w1v.z + xv.w * w1v.w;
        b += xv.x * w2v.x + xv.y * w2v.y + xv.z * w2v.z + xv.w * w2v.w;
    }
    #pragma unroll
    for (int o = 16; o; o >>= 1) {
        a += __shfl_xor_sync(0xffffffffu, a, o);
        b += __shfl_xor_sync(0xffffffffu, b, o);
    }
    if (lane == 0) { g_p[gw] = a; g_q[gw] = b; }
}

// ---------------------------------------------------------------------------
// Kernel 2: per-batch scan of start flags -> word boundaries + n_words.
// ---------------------------------------------------------------------------
__global__ void k_scan(const float* __restrict__ bscore_p,
                       int S, float* __restrict__ tail)
{
    const int T = 256;
    int b   = blockIdx.x;
    int tid = threadIdx.x;
    int chunk = (S + T - 1) / T;
    if (chunk > 16) chunk = 16;

    const float* pb = g_p + (size_t)b * S;
    const float* qb = g_q + (size_t)b * S;
    float bsc = *bscore_p;

    int local[16];
    int sum = 0;
    for (int i = 0; i < chunk; i++) {
        int t = tid * chunk + i;
        int st = 0;
        if (t > 0 && t < S) {
            float sc = pb[t - 1] + qb[t] + bsc;
            st = (sc > 0.5f) ? 0 : 1;
        }
        sum += st;
        local[i] = sum;
    }

    int lane = tid & 31, w = tid >> 5;
    int v = sum;
    #pragma unroll
    for (int o = 1; o < 32; o <<= 1) {
        int n = __shfl_up_sync(0xffffffffu, v, o);
        if (lane >= o) v += n;
    }
    __shared__ int wsum[8];
    __shared__ int woff[9];
    if (lane == 31) wsum[w] = v;
    __syncthreads();
    if (tid == 0) {
        int acc = 0;
        for (int i = 0; i < 8; i++) { woff[i] = acc; acc += wsum[i]; }
        woff[8] = acc;
    }
    __syncthreads();

    int excl = woff[w] + (v - sum);
    int* wsb = g_wstart + (size_t)b * (S + 1);
    for (int i = 0; i < chunk; i++) {
        int t = tid * chunk + i;
        if (t < S) {
            int stflag = local[i] - (i ? local[i - 1] : 0);
            int seg = excl + local[i];
            if (t == 0 || stflag) wsb[seg] = t;
        }
    }
    if (tid == 0) {
        int nw = woff[8] + 1;
        wsb[nw] = S;
        g_nw[b] = nw;
        if (tail) tail[b] = (float)nw;
    }
}

// ---------------------------------------------------------------------------
// Kernel W: w_comb -> half, k-pair interleaved: Wh[k>>1][n*2 + (k&1)].
// ---------------------------------------------------------------------------
__global__ void k_prep_w(const float* __restrict__ w)
{
    int idx = blockIdx.x * blockDim.x + threadIdx.x;   // 512*512 elems
    int k = idx >> 9, n = idx & 511;
    g_Wh[(size_t)(k >> 1) * 1024 + (n << 1) + (k & 1)] = __float2half_rn(w[idx]);
}

// ---------------------------------------------------------------------------
// Kernel 3: segment mean of frames -> g_Mh (half, valid words only).
// ---------------------------------------------------------------------------
__global__ void k_segmean(const float* __restrict__ frame, int S, int D)
{
    int b = blockIdx.y, s = blockIdx.x;
    if (s >= g_nw[b]) return;
    const int* wsb = g_wstart + (size_t)b * (S + 1);
    int st = wsb[s], en = wsb[s + 1];
    float inv = 1.f / (float)(en - st);
    int n4 = D >> 2;
    const float4* fb = (const float4*)(frame + ((size_t)b * S) * D);
    __half2* mr = (__half2*)(g_Mh + ((size_t)b * S + s) * D);
    for (int i = threadIdx.x; i < n4; i += blockDim.x) {
        float4 acc = make_float4(0.f, 0.f, 0.f, 0.f);
        for (int t = st; t < en; t++) {
            float4 v = fb[(size_t)t * n4 + i];
            acc.x += v.x; acc.y += v.y; acc.z += v.z; acc.w += v.w;
        }
        mr[i * 2]     = __floats2half2_rn(acc.x * inv, acc.y * inv);
        mr[i * 2 + 1] = __floats2half2_rn(acc.z * inv, acc.w * inv);
    }
}

// ---------------------------------------------------------------------------
// Kernel 4: mma.sync f16 GEMM.  out[BS,512] = Mh[BS,512] @ W[512,512]
// (+bias, zero rows with s >= n_words[b]).
// Block tile 128x128x32, 8 warps of 64x32, double-buffered cp.async.
// Smem A: [128][56] halves (112B stride)   -> conflict-free frag loads
// Smem B: [16 pair-rows][264] halves (528B stride), k-pair interleaved.
// ---------------------------------------------------------------------------
#define MH_ASTRIDE 56
#define MH_ABYTES  (128 * MH_ASTRIDE * 2)       // 14336
#define MH_BSTRIDE 264
#define MH_BBYTES  (16 * MH_BSTRIDE * 2)        // 8448
#define MH_STAGE   (MH_ABYTES + MH_BBYTES)      // 22784
#define MH_SMEM    (2 * MH_STAGE)               // 45568

__device__ __forceinline__ void mh_load(uint32_t base, int stage,
                                        long m0, int n0, int k0, int tid)
{
    uint32_t a_s = base + (uint32_t)stage * MH_STAGE;
    uint32_t b_s = a_s + MH_ABYTES;
    #pragma unroll
    for (int j = 0; j < 2; j++) {                // A: 128 rows x 32 halves (64B)
        int L = tid + 256 * j;
        int row = L >> 2, seg = L & 3;
        cp16(a_s + (uint32_t)row * (MH_ASTRIDE * 2) + (uint32_t)seg * 16,
             g_Mh + (m0 + row) * 512 + k0 + seg * 8);
    }
    #pragma unroll
    for (int j = 0; j < 2; j++) {                // B: 16 pair-rows x 256 halves (512B)
        int L = tid + 256 * j;
        int row = L >> 5, seg = L & 31;
        cp16(b_s + (uint32_t)row * (MH_BSTRIDE * 2) + (uint32_t)seg * 16,
             g_Wh + (size_t)((k0 >> 1) + row) * 1024 + (n0 << 1) + seg * 8);
    }
    asm volatile("cp.async.commit_group;" ::: "memory");
}

__global__ __launch_bounds__(256, 2)
void k_tgemm_mma(const float* __restrict__ bcomb,
                 float* __restrict__ out, int S)
{
    extern __shared__ char smem[];
    uint32_t base = smem_u32(smem);

    int tid  = threadIdx.x;
    long m0 = (long)blockIdx.y * 128;
    int  n0 = blockIdx.x * 128;

    // ---- fully-invalid tile: zero-fill our column strip and exit ----
    {
        int b0 = (int)(m0 / S);
        int s0 = (int)(m0 - (long)b0 * S);
        if (s0 + 128 <= S && s0 >= g_nw[b0]) {
            float4 z = make_float4(0.f, 0.f, 0.f, 0.f);
            #pragma unroll
            for (int j = 0; j < 16; j++) {
                int L = tid + 256 * j;              // 4096 float4 slots
                int row = L >> 5, seg = L & 31;
                *(float4*)(out + (m0 + row) * 512 + n0 + seg * 4) = z;
            }
            return;
        }
    }

    int lane = tid & 31;
    int wid  = tid >> 5;
    int wm   = wid & 1;          // 0/1 -> 64-row half
    int wn   = wid >> 1;         // 0..3 -> 32-col quarter
    int g    = lane >> 2;        // groupID
    int t    = lane & 3;         // threadID_in_group

    float c[4][4][4];
    #pragma unroll
    for (int i = 0; i < 4; i++)
        #pragma unroll
        for (int j = 0; j < 4; j++)
            #pragma unroll
            for (int r = 0; r < 4; r++) c[i][j][r] = 0.f;

    mh_load(base, 0, m0, n0, 0, tid);

    #pragma unroll 1
    for (int ch = 0; ch < 16; ch++) {
        if (ch + 1 < 16) {
            mh_load(base, (ch + 1) & 1, m0, n0, (ch + 1) * 32, tid);
            asm volatile("cp.async.wait_group 1;" ::: "memory");
        } else {
            asm volatile("cp.async.wait_group 0;" ::: "memory");
        }
        __syncthreads();

        const __half* As = (const __half*)(smem + (size_t)(ch & 1) * MH_STAGE);
        const __half* Bs = (const __half*)(smem + (size_t)(ch & 1) * MH_STAGE + MH_ABYTES);

        #pragma unroll
        for (int kk = 0; kk < 32; kk += 16) {
            uint32_t af[4][4];
            #pragma unroll
            for (int mt = 0; mt < 4; mt++) {
                int r0 = wm * 64 + mt * 16 + g;
                const __half* ap = As + (size_t)r0 * MH_ASTRIDE + kk + 2 * t;
                af[mt][0] = *(const uint32_t*)(ap);
                af[mt][1] = *(const uint32_t*)(ap + 8 * MH_ASTRIDE);
                af[mt][2] = *(const uint32_t*)(ap + 8);
                af[mt][3] = *(const uint32_t*)(ap + 8 * MH_ASTRIDE + 8);
            }
            uint32_t bf[4][2];
            #pragma unroll
            for (int nt = 0; nt < 4; nt++) {
                int col = wn * 32 + nt * 8 + g;
                const __half* bp = Bs + (size_t)((kk >> 1) + t) * MH_BSTRIDE + col * 2;
                bf[nt][0] = *(const uint32_t*)(bp);
                bf[nt][1] = *(const uint32_t*)(bp + 4 * MH_BSTRIDE);
            }
            #pragma unroll
            for (int mt = 0; mt < 4; mt++)
                #pragma unroll
                for (int nt = 0; nt < 4; nt++)
                    mma_f16(c[mt][nt], af[mt], bf[nt]);
        }
        __syncthreads();
    }

    // epilogue: bias + validity mask, float2 stores
    #pragma unroll
    for (int mt = 0; mt < 4; mt++) {
        #pragma unroll
        for (int half = 0; half < 2; half++) {
            long grow = m0 + wm * 64 + mt * 16 + g + half * 8;
            int b = (int)(grow / S);
            int s = (int)(grow - (long)b * S);
            bool valid = s < g_nw[b];
            float* orow = out + grow * 512 + n0;
            #pragma unroll
            for (int nt = 0; nt < 4; nt++) {
                int col = wn * 32 + nt * 8 + t * 2;
                float2 v;
                if (valid) {
                    v.x = c[mt][nt][half * 2 + 0] + bcomb[n0 + col];
                    v.y = c[mt][nt][half * 2 + 1] + bcomb[n0 + col + 1];
                } else {
                    v.x = 0.f; v.y = 0.f;
                }
                *(float2*)(orow + col) = v;
            }
        }
    }
}

// ---------------------------------------------------------------------------
// Fallback SIMT path (D != 512): fp32 SGEMM + segment-average.
// ---------------------------------------------------------------------------
#define BM 128
#define BN 128
#define BK 8
__global__ __launch_bounds__(256, 2)
void k_gemm(const float* __restrict__ A, const float* __restrict__ Wm,
            int M, int N, int K)
{
    __shared__ float As[2][BK][BM];
    __shared__ float Bs[2][BK][BN];
    int bx = blockIdx.x, by = blockIdx.y;
    int tid = threadIdx.x;
    int tx = tid & 15, ty = tid >> 4;
    int arow = tid >> 1, acol = (tid & 1) * 4;
    int brow = tid >> 5, bcol = (tid & 31) * 4;
    const float* Ap = A + ((size_t)(by * BM + arow)) * K + acol;
    const float* Bp = Wm + (size_t)brow * N + bx * BN + bcol;

    float acc[8][8];
    #pragma unroll
    for (int i = 0; i < 8; i++)
        #pragma unroll
        for (int j = 0; j < 8; j++) acc[i][j] = 0.f;

    float4 a4 = *(const float4*)Ap;
    float4 b4 = *(const float4*)Bp;
    As[0][acol + 0][arow] = a4.x; As[0][acol + 1][arow] = a4.y;
    As[0][acol + 2][arow] = a4.z; As[0][acol + 3][arow] = a4.w;
    *(float4*)&Bs[0][brow][bcol] = b4;
    __syncthreads();

    int buf = 0;
    for (int k0 = 0; k0 < K; k0 += BK) {
        bool more = (k0 + BK) < K;
        float4 na, nb;
        if (more) {
            na = *(const float4*)(Ap + (k0 + BK));
            nb = *(const float4*)(Bp + (size_t)(k0 + BK) * N);
        }
        #pragma unroll
        for (int k = 0; k < BK; k++) {
            float ra[8], rb[8];
            *(float4*)(ra + 0) = *(float4*)&As[buf][k][ty * 4];
            *(float4*)(ra + 4) = *(float4*)&As[buf][k][64 + ty * 4];
            *(float4*)(rb + 0) = *(float4*)&Bs[buf][k][tx * 4];
            *(float4*)(rb + 4) = *(float4*)&Bs[buf][k][64 + tx * 4];
            #pragma unroll
            for (int i = 0; i < 8; i++)
                #pragma unroll
                for (int j = 0; j < 8; j++)
                    acc[i][j] = fmaf(ra[i], rb[j], acc[i][j]);
        }
        if (more) {
            int nxt = buf ^ 1;
            As[nxt][acol + 0][arow] = na.x; As[nxt][acol + 1][arow] = na.y;
            As[nxt][acol + 2][arow] = na.z; As[nxt][acol + 3][arow] = na.w;
            *(float4*)&Bs[nxt][brow][bcol] = nb;
            __syncthreads();
            buf = nxt;
        }
    }
    #pragma unroll
    for (int i = 0; i < 8; i++) {
        int r = by * BM + ((i < 4) ? (ty * 4 + i) : (64 + ty * 4 + i - 4));
        float* crow = g_Y + (size_t)r * N + bx * BN;
        *(float4*)(crow + tx * 4)      = make_float4(acc[i][0], acc[i][1], acc[i][2], acc[i][3]);
        *(float4*)(crow + 64 + tx * 4) = make_float4(acc[i][4], acc[i][5], acc[i][6], acc[i][7]);
    }
}

__global__ void k_avg(const float* __restrict__ bcomb,
                      float* __restrict__ out, int S, int D)
{
    int b = blockIdx.y, s = blockIdx.x;
    int n4 = D >> 2;
    float4* orow = (float4*)(out + ((size_t)b * S + s) * D);
    int nw = g_nw[b];
    if (s >= nw) {
        for (int i = threadIdx.x; i < n4; i += blockDim.x)
            orow[i] = make_float4(0.f, 0.f, 0.f, 0.f);
        return;
    }
    const int* wsb = g_wstart + (size_t)b * (S + 1);
    int st = wsb[s], en = wsb[s + 1];
    float inv = 1.f / (float)(en - st);
    const float4* ybase = (const float4*)(g_Y + ((size_t)b * S) * D);
    const float4* bc4 = (const float4*)bcomb;
    for (int i = threadIdx.x; i < n4; i += blockDim.x) {
        float4 acc = make_float4(0.f, 0.f, 0.f, 0.f);
        for (int tt = st; tt < en; tt++) {
            float4 v = ybase[(size_t)tt * n4 + i];
            acc.x += v.x; acc.y += v.y; acc.z += v.z; acc.w += v.w;
        }
        float4 bb = bc4[i];
        orow[i] = make_float4(acc.x * inv + bb.x, acc.y * inv + bb.y,
                              acc.z * inv + bb.z, acc.w * inv + bb.w);
    }
}

// ---------------------------------------------------------------------------
extern "C" void kernel_launch(void* const* d_in, const int* in_sizes, int n_in,
                              void* d_out, int out_size)
{
    const float* frame  = (const float*)d_in[0];
    const float* wscore = (const float*)d_in[1];
    const float* bscore = (const float*)d_in[2];
    const float* wcomb  = (const float*)d_in[3];
    const float* bcomb  = (const float*)d_in[4];
    float* out = (float*)d_out;

    int D   = in_sizes[1] / 2;
    long total = in_sizes[0];
    int BS  = (int)(total / D);

    int B = out_size - (int)total;
    if (B <= 0 || B > MAX_B || (BS % B) != 0) {
        B = 16;
        while (B > 1 && (BS % B) != 0) B >>= 1;
    }
    int S = BS / B;
    float* tail = (out_size == (int)total + B) ? (out + total) : nullptr;

    // 1) per-frame score dots
    {
        int wpb = 8;
        int blocks = (BS + wpb - 1) / wpb;
        k_score<<<blocks, wpb * 32>>>(frame, wscore, D, BS);
    }
    // 2) per-batch scan
    k_scan<<<B, 256>>>(bscore, S, tail);

    if (D == 512 && (BS % 128) == 0) {
        // --- tensor path (mma.sync m16n8k16 f16) ---
        k_prep_w<<<512 * 512 / 256, 256>>>(wcomb);
        {
            dim3 grid(S, B);
            k_segmean<<<grid, 128>>>(frame, S, D);
        }
        static int smem_set = 0;
        if (!smem_set) {
            cudaFuncSetAttribute(k_tgemm_mma,
                                 cudaFuncAttributeMaxDynamicSharedMemorySize, MH_SMEM);
            smem_set = 1;
        }
        dim3 grid(512 / 128, BS / 128);
        k_tgemm_mma<<<grid, 256, MH_SMEM>>>(bcomb, out, S);
    } else {
        // --- fallback SIMT path ---
        dim3 grid(D / BN, BS / BM);
        k_gemm<<<grid, 256>>>(frame, wcomb, BS, D, D);
        dim3 agrid(S, B);
        k_avg<<<agrid, 128>>>(bcomb, out, S, D);
    }
}

// round 7
// speedup vs baseline: 3.7022x; 1.0766x over previous
#include <cuda_runtime.h>
#include <cuda_bf16.h>
#include <cuda_fp16.h>
#include <cstdint>

// ===========================================================================
// WordSpeechContinuousFusion  (B=16, S=2048, D=512)
//
//   k_score     : p[i]=frame_i.w1, q[i]=frame_i.w2          (1 frame read)
//   k_scan      : per-batch scan of start flags -> word_start[], n_words[]
//   k_prep_w    : Wh = half(w_comb), k-pair-interleaved layout
//   k_segmean_w : Mh[b,s] = half(mean(frame[st:en]))  (warp/word, MLP=4)
//   k_tgemm_mma : out = Mh @ Wh (+bias, mask), m16n8k16 f16, 4-stage pipeline
//
// Fallback SIMT path retained for D != 512.
// ===========================================================================

#define MAX_BS   65536
#define MAX_B    4096
#define Y_ELEMS  ((size_t)1 << 24)   // fallback scratch (fp32)

__device__ float  g_p[MAX_BS];
__device__ float  g_q[MAX_BS];
__device__ float  g_Y[Y_ELEMS];                 // fallback path only
__device__ __half g_Mh[(size_t)MAX_BS * 512];   // segmean, half
__device__ __half g_Wh[256 * 1024];             // w_comb, half, k-pair interleaved
__device__ int    g_wstart[MAX_BS + MAX_B + 1];
__device__ int    g_nw[MAX_B];

// ---------------------------------------------------------------------------
__device__ __forceinline__ uint32_t smem_u32(const void* p) {
    uint32_t a;
    asm("{ .reg .u64 t; cvta.to.shared.u64 t, %1; cvt.u32.u64 %0, t; }"
        : "=r"(a) : "l"(p));
    return a;
}
__device__ __forceinline__ void cp16(uint32_t dst, const void* src) {
    asm volatile("cp.async.cg.shared.global [%0], [%1], 16;" :: "r"(dst), "l"(src));
}
__device__ __forceinline__ void mma_f16(float* c, const uint32_t* a, const uint32_t* b) {
    asm volatile(
        "mma.sync.aligned.m16n8k16.row.col.f32.f16.f16.f32 "
        "{%0,%1,%2,%3}, {%4,%5,%6,%7}, {%8,%9}, {%0,%1,%2,%3};"
        : "+f"(c[0]), "+f"(c[1]), "+f"(c[2]), "+f"(c[3])
        : "r"(a[0]), "r"(a[1]), "r"(a[2]), "r"(a[3]), "r"(b[0]), "r"(b[1]));
}

// ---------------------------------------------------------------------------
// Kernel 1: per-frame dots with the two halves of w_score (warp per frame).
// ---------------------------------------------------------------------------
__global__ void k_score(const float* __restrict__ x,
                        const float* __restrict__ wscore,
                        int D, int BS)
{
    int gw   = (blockIdx.x * blockDim.x + threadIdx.x) >> 5;
    int lane = threadIdx.x & 31;
    if (gw >= BS) return;

    const float4* f  = (const float4*)(x + (size_t)gw * D);
    const float4* w1 = (const float4*)(wscore);
    const float4* w2 = (const float4*)(wscore + D);
    int n4 = D >> 2;

    float a = 0.f, b = 0.f;
    for (int i = lane; i < n4; i += 32) {
        float4 xv = f[i];
        float4 w1v = w1[i];
        float4 w2v = w2[i];
        a += xv.x * w1v.x + xv.y * w1v.y + xv.z * w1v.z + xv.w * w1v.w;
        b += xv.x * w2v.x + xv.y * w2v.y + xv.z * w2v.z + xv.w * w2v.w;
    }
    #pragma unroll
    for (int o = 16; o; o >>= 1) {
        a += __shfl_xor_sync(0xffffffffu, a, o);
        b += __shfl_xor_sync(0xffffffffu, b, o);
    }
    if (lane == 0) { g_p[gw] = a; g_q[gw] = b; }
}

// ---------------------------------------------------------------------------
// Kernel 2: per-batch scan of start flags -> word boundaries + n_words.
// ---------------------------------------------------------------------------
__global__ void k_scan(const float* __restrict__ bscore_p,
                       int S, float* __restrict__ tail)
{
    const int T = 256;
    int b   = blockIdx.x;
    int tid = threadIdx.x;
    int chunk = (S + T - 1) / T;
    if (chunk > 16) chunk = 16;

    const float* pb = g_p + (size_t)b * S;
    const float* qb = g_q + (size_t)b * S;
    float bsc = *bscore_p;

    int local[16];
    int sum = 0;
    for (int i = 0; i < chunk; i++) {
        int t = tid * chunk + i;
        int st = 0;
        if (t > 0 && t < S) {
            float sc = pb[t - 1] + qb[t] + bsc;
            st = (sc > 0.5f) ? 0 : 1;
        }
        sum += st;
        local[i] = sum;
    }

    int lane = tid & 31, w = tid >> 5;
    int v = sum;
    #pragma unroll
    for (int o = 1; o < 32; o <<= 1) {
        int n = __shfl_up_sync(0xffffffffu, v, o);
        if (lane >= o) v += n;
    }
    __shared__ int wsum[8];
    __shared__ int woff[9];
    if (lane == 31) wsum[w] = v;
    __syncthreads();
    if (tid == 0) {
        int acc = 0;
        for (int i = 0; i < 8; i++) { woff[i] = acc; acc += wsum[i]; }
        woff[8] = acc;
    }
    __syncthreads();

    int excl = woff[w] + (v - sum);
    int* wsb = g_wstart + (size_t)b * (S + 1);
    for (int i = 0; i < chunk; i++) {
        int t = tid * chunk + i;
        if (t < S) {
            int stflag = local[i] - (i ? local[i - 1] : 0);
            int seg = excl + local[i];
            if (t == 0 || stflag) wsb[seg] = t;
        }
    }
    if (tid == 0) {
        int nw = woff[8] + 1;
        wsb[nw] = S;
        g_nw[b] = nw;
        if (tail) tail[b] = (float)nw;
    }
}

// ---------------------------------------------------------------------------
// Kernel W: w_comb -> half, k-pair interleaved: Wh[k>>1][n*2 + (k&1)].
// ---------------------------------------------------------------------------
__global__ void k_prep_w(const float* __restrict__ w)
{
    int idx = blockIdx.x * blockDim.x + threadIdx.x;   // 512*512 elems
    int k = idx >> 9, n = idx & 511;
    g_Wh[(size_t)(k >> 1) * 1024 + (n << 1) + (k & 1)] = __float2half_rn(w[idx]);
}

// ---------------------------------------------------------------------------
// Kernel 3: segment mean -> g_Mh (half). One warp per word, MLP=4 per lane.
// D fixed at 512 (tensor path only).
// ---------------------------------------------------------------------------
__global__ void k_segmean_w(const float* __restrict__ frame, int S, int BS)
{
    int word = blockIdx.x * 8 + (threadIdx.x >> 5);
    if (word >= BS) return;
    int lane = threadIdx.x & 31;
    int b = word / S, s = word - b * S;
    if (s >= g_nw[b]) return;

    const int* wsb = g_wstart + (size_t)b * (S + 1);
    int st = wsb[s], en = wsb[s + 1];
    float inv = 1.f / (float)(en - st);

    const float4* fb = (const float4*)(frame + ((size_t)b * S) * 512);
    float4 acc[4];
    #pragma unroll
    for (int j = 0; j < 4; j++) acc[j] = make_float4(0.f, 0.f, 0.f, 0.f);

    for (int t = st; t < en; t++) {
        const float4* row = fb + (size_t)t * 128;
        #pragma unroll
        for (int j = 0; j < 4; j++) {
            float4 v = row[lane + j * 32];
            acc[j].x += v.x; acc[j].y += v.y; acc[j].z += v.z; acc[j].w += v.w;
        }
    }
    __half2* mr = (__half2*)(g_Mh + ((size_t)b * S + s) * 512);
    #pragma unroll
    for (int j = 0; j < 4; j++) {
        int i = lane + j * 32;
        mr[i * 2]     = __floats2half2_rn(acc[j].x * inv, acc[j].y * inv);
        mr[i * 2 + 1] = __floats2half2_rn(acc[j].z * inv, acc[j].w * inv);
    }
}

// ---------------------------------------------------------------------------
// Kernel 4: mma.sync f16 GEMM, 4-stage cp.async pipeline.
// out[BS,512] = Mh[BS,512] @ W[512,512] (+bias, mask).
// Block tile 128x128x32, 8 warps of 64x32.
// ---------------------------------------------------------------------------
#define MH_ASTRIDE 56
#define MH_ABYTES  (128 * MH_ASTRIDE * 2)       // 14336
#define MH_BSTRIDE 264
#define MH_BBYTES  (16 * MH_BSTRIDE * 2)        // 8448
#define MH_STAGE   (MH_ABYTES + MH_BBYTES)      // 22784
#define MH_NSTAGE  4
#define MH_SMEM    (MH_NSTAGE * MH_STAGE)       // 91136

__device__ __forceinline__ void mh_load(uint32_t base, int stage,
                                        long m0, int n0, int k0, int tid)
{
    uint32_t a_s = base + (uint32_t)stage * MH_STAGE;
    uint32_t b_s = a_s + MH_ABYTES;
    #pragma unroll
    for (int j = 0; j < 2; j++) {                // A: 128 rows x 32 halves (64B)
        int L = tid + 256 * j;
        int row = L >> 2, seg = L & 3;
        cp16(a_s + (uint32_t)row * (MH_ASTRIDE * 2) + (uint32_t)seg * 16,
             g_Mh + (m0 + row) * 512 + k0 + seg * 8);
    }
    #pragma unroll
    for (int j = 0; j < 2; j++) {                // B: 16 pair-rows x 256 halves (512B)
        int L = tid + 256 * j;
        int row = L >> 5, seg = L & 31;
        cp16(b_s + (uint32_t)row * (MH_BSTRIDE * 2) + (uint32_t)seg * 16,
             g_Wh + (size_t)((k0 >> 1) + row) * 1024 + (n0 << 1) + seg * 8);
    }
    asm volatile("cp.async.commit_group;" ::: "memory");
}

__global__ __launch_bounds__(256, 2)
void k_tgemm_mma(const float* __restrict__ bcomb,
                 float* __restrict__ out, int S)
{
    extern __shared__ char smem[];
    uint32_t base = smem_u32(smem);

    int tid  = threadIdx.x;
    long m0 = (long)blockIdx.y * 128;
    int  n0 = blockIdx.x * 128;

    // ---- fully-invalid tile: zero-fill our column strip and exit ----
    {
        int b0 = (int)(m0 / S);
        int s0 = (int)(m0 - (long)b0 * S);
        if (s0 + 128 <= S && s0 >= g_nw[b0]) {
            float4 z = make_float4(0.f, 0.f, 0.f, 0.f);
            #pragma unroll
            for (int j = 0; j < 16; j++) {
                int L = tid + 256 * j;              // 4096 float4 slots
                int row = L >> 5, seg = L & 31;
                *(float4*)(out + (m0 + row) * 512 + n0 + seg * 4) = z;
            }
            return;
        }
    }

    int lane = tid & 31;
    int wid  = tid >> 5;
    int wm   = wid & 1;          // 0/1 -> 64-row half
    int wn   = wid >> 1;         // 0..3 -> 32-col quarter
    int g    = lane >> 2;        // groupID
    int t    = lane & 3;         // threadID_in_group

    float c[4][4][4];
    #pragma unroll
    for (int i = 0; i < 4; i++)
        #pragma unroll
        for (int j = 0; j < 4; j++)
            #pragma unroll
            for (int r = 0; r < 4; r++) c[i][j][r] = 0.f;

    // prologue: 3 stages in flight
    mh_load(base, 0, m0, n0, 0, tid);
    mh_load(base, 1, m0, n0, 32, tid);
    mh_load(base, 2, m0, n0, 64, tid);

    #pragma unroll 1
    for (int ch = 0; ch < 16; ch++) {
        if (ch <= 13)      asm volatile("cp.async.wait_group 2;" ::: "memory");
        else if (ch == 14) asm volatile("cp.async.wait_group 1;" ::: "memory");
        else               asm volatile("cp.async.wait_group 0;" ::: "memory");
        __syncthreads();   // stage ch resident; all warps done with stage (ch-1)

        if (ch + 3 < 16)
            mh_load(base, (ch + 3) & 3, m0, n0, (ch + 3) * 32, tid);

        const __half* As = (const __half*)(smem + (size_t)(ch & 3) * MH_STAGE);
        const __half* Bs = (const __half*)(smem + (size_t)(ch & 3) * MH_STAGE + MH_ABYTES);

        #pragma unroll
        for (int kk = 0; kk < 32; kk += 16) {
            uint32_t af[4][4];
            #pragma unroll
            for (int mt = 0; mt < 4; mt++) {
                int r0 = wm * 64 + mt * 16 + g;
                const __half* ap = As + (size_t)r0 * MH_ASTRIDE + kk + 2 * t;
                af[mt][0] = *(const uint32_t*)(ap);
                af[mt][1] = *(const uint32_t*)(ap + 8 * MH_ASTRIDE);
                af[mt][2] = *(const uint32_t*)(ap + 8);
                af[mt][3] = *(const uint32_t*)(ap + 8 * MH_ASTRIDE + 8);
            }
            uint32_t bf[4][2];
            #pragma unroll
            for (int nt = 0; nt < 4; nt++) {
                int col = wn * 32 + nt * 8 + g;
                const __half* bp = Bs + (size_t)((kk >> 1) + t) * MH_BSTRIDE + col * 2;
                bf[nt][0] = *(const uint32_t*)(bp);
                bf[nt][1] = *(const uint32_t*)(bp + 4 * MH_BSTRIDE);
            }
            #pragma unroll
            for (int mt = 0; mt < 4; mt++)
                #pragma unroll
                for (int nt = 0; nt < 4; nt++)
                    mma_f16(c[mt][nt], af[mt], bf[nt]);
        }
    }

    // epilogue: bias + validity mask, float2 stores
    #pragma unroll
    for (int mt = 0; mt < 4; mt++) {
        #pragma unroll
        for (int half = 0; half < 2; half++) {
            long grow = m0 + wm * 64 + mt * 16 + g + half * 8;
            int b = (int)(grow / S);
            int s = (int)(grow - (long)b * S);
            bool valid = s < g_nw[b];
            float* orow = out + grow * 512 + n0;
            #pragma unroll
            for (int nt = 0; nt < 4; nt++) {
                int col = wn * 32 + nt * 8 + t * 2;
                float2 v;
                if (valid) {
                    v.x = c[mt][nt][half * 2 + 0] + bcomb[n0 + col];
                    v.y = c[mt][nt][half * 2 + 1] + bcomb[n0 + col + 1];
                } else {
                    v.x = 0.f; v.y = 0.f;
                }
                *(float2*)(orow + col) = v;
            }
        }
    }
}

// ---------------------------------------------------------------------------
// Fallback SIMT path (D != 512): fp32 SGEMM + segment-average.
// ---------------------------------------------------------------------------
#define BM 128
#define BN 128
#define BK 8
__global__ __launch_bounds__(256, 2)
void k_gemm(const float* __restrict__ A, const float* __restrict__ Wm,
            int M, int N, int K)
{
    __shared__ float As[2][BK][BM];
    __shared__ float Bs[2][BK][BN];
    int bx = blockIdx.x, by = blockIdx.y;
    int tid = threadIdx.x;
    int tx = tid & 15, ty = tid >> 4;
    int arow = tid >> 1, acol = (tid & 1) * 4;
    int brow = tid >> 5, bcol = (tid & 31) * 4;
    const float* Ap = A + ((size_t)(by * BM + arow)) * K + acol;
    const float* Bp = Wm + (size_t)brow * N + bx * BN + bcol;

    float acc[8][8];
    #pragma unroll
    for (int i = 0; i < 8; i++)
        #pragma unroll
        for (int j = 0; j < 8; j++) acc[i][j] = 0.f;

    float4 a4 = *(const float4*)Ap;
    float4 b4 = *(const float4*)Bp;
    As[0][acol + 0][arow] = a4.x; As[0][acol + 1][arow] = a4.y;
    As[0][acol + 2][arow] = a4.z; As[0][acol + 3][arow] = a4.w;
    *(float4*)&Bs[0][brow][bcol] = b4;
    __syncthreads();

    int buf = 0;
    for (int k0 = 0; k0 < K; k0 += BK) {
        bool more = (k0 + BK) < K;
        float4 na, nb;
        if (more) {
            na = *(const float4*)(Ap + (k0 + BK));
            nb = *(const float4*)(Bp + (size_t)(k0 + BK) * N);
        }
        #pragma unroll
        for (int k = 0; k < BK; k++) {
            float ra[8], rb[8];
            *(float4*)(ra + 0) = *(float4*)&As[buf][k][ty * 4];
            *(float4*)(ra + 4) = *(float4*)&As[buf][k][64 + ty * 4];
            *(float4*)(rb + 0) = *(float4*)&Bs[buf][k][tx * 4];
            *(float4*)(rb + 4) = *(float4*)&Bs[buf][k][64 + tx * 4];
            #pragma unroll
            for (int i = 0; i < 8; i++)
                #pragma unroll
                for (int j = 0; j < 8; j++)
                    acc[i][j] = fmaf(ra[i], rb[j], acc[i][j]);
        }
        if (more) {
            int nxt = buf ^ 1;
            As[nxt][acol + 0][arow] = na.x; As[nxt][acol + 1][arow] = na.y;
            As[nxt][acol + 2][arow] = na.z; As[nxt][acol + 3][arow] = na.w;
            *(float4*)&Bs[nxt][brow][bcol] = nb;
            __syncthreads();
            buf = nxt;
        }
    }
    #pragma unroll
    for (int i = 0; i < 8; i++) {
        int r = by * BM + ((i < 4) ? (ty * 4 + i) : (64 + ty * 4 + i - 4));
        float* crow = g_Y + (size_t)r * N + bx * BN;
        *(float4*)(crow + tx * 4)      = make_float4(acc[i][0], acc[i][1], acc[i][2], acc[i][3]);
        *(float4*)(crow + 64 + tx * 4) = make_float4(acc[i][4], acc[i][5], acc[i][6], acc[i][7]);
    }
}

__global__ void k_avg(const float* __restrict__ bcomb,
                      float* __restrict__ out, int S, int D)
{
    int b = blockIdx.y, s = blockIdx.x;
    int n4 = D >> 2;
    float4* orow = (float4*)(out + ((size_t)b * S + s) * D);
    int nw = g_nw[b];
    if (s >= nw) {
        for (int i = threadIdx.x; i < n4; i += blockDim.x)
            orow[i] = make_float4(0.f, 0.f, 0.f, 0.f);
        return;
    }
    const int* wsb = g_wstart + (size_t)b * (S + 1);
    int st = wsb[s], en = wsb[s + 1];
    float inv = 1.f / (float)(en - st);
    const float4* ybase = (const float4*)(g_Y + ((size_t)b * S) * D);
    const float4* bc4 = (const float4*)bcomb;
    for (int i = threadIdx.x; i < n4; i += blockDim.x) {
        float4 acc = make_float4(0.f, 0.f, 0.f, 0.f);
        for (int tt = st; tt < en; tt++) {
            float4 v = ybase[(size_t)tt * n4 + i];
            acc.x += v.x; acc.y += v.y; acc.z += v.z; acc.w += v.w;
        }
        float4 bb = bc4[i];
        orow[i] = make_float4(acc.x * inv + bb.x, acc.y * inv + bb.y,
                              acc.z * inv + bb.z, acc.w * inv + bb.w);
    }
}

// ---------------------------------------------------------------------------
extern "C" void kernel_launch(void* const* d_in, const int* in_sizes, int n_in,
                              void* d_out, int out_size)
{
    const float* frame  = (const float*)d_in[0];
    const float* wscore = (const float*)d_in[1];
    const float* bscore = (const float*)d_in[2];
    const float* wcomb  = (const float*)d_in[3];
    const float* bcomb  = (const float*)d_in[4];
    float* out = (float*)d_out;

    int D   = in_sizes[1] / 2;
    long total = in_sizes[0];
    int BS  = (int)(total / D);

    int B = out_size - (int)total;
    if (B <= 0 || B > MAX_B || (BS % B) != 0) {
        B = 16;
        while (B > 1 && (BS % B) != 0) B >>= 1;
    }
    int S = BS / B;
    float* tail = (out_size == (int)total + B) ? (out + total) : nullptr;

    // 1) per-frame score dots
    {
        int wpb = 8;
        int blocks = (BS + wpb - 1) / wpb;
        k_score<<<blocks, wpb * 32>>>(frame, wscore, D, BS);
    }
    // 2) per-batch scan
    k_scan<<<B, 256>>>(bscore, S, tail);

    if (D == 512 && (BS % 128) == 0) {
        // --- tensor path (mma.sync m16n8k16 f16, 4-stage pipeline) ---
        k_prep_w<<<512 * 512 / 256, 256>>>(wcomb);
        k_segmean_w<<<(BS + 7) / 8, 256>>>(frame, S, BS);
        static int smem_set = 0;
        if (!smem_set) {
            cudaFuncSetAttribute(k_tgemm_mma,
                                 cudaFuncAttributeMaxDynamicSharedMemorySize, MH_SMEM);
            smem_set = 1;
        }
        dim3 grid(512 / 128, BS / 128);
        k_tgemm_mma<<<grid, 256, MH_SMEM>>>(bcomb, out, S);
    } else {
        // --- fallback SIMT path ---
        dim3 grid(D / BN, BS / BM);
        k_gemm<<<grid, 256>>>(frame, wcomb, BS, D, D);
        dim3 agrid(S, B);
        k_avg<<<agrid, 128>>>(bcomb, out, S, D);
    }
}

// round 8
// speedup vs baseline: 3.9554x; 1.0684x over previous
#include <cuda_runtime.h>
#include <cuda_bf16.h>
#include <cuda_fp16.h>
#include <cstdint>

// ===========================================================================
// WordSpeechContinuousFusion  (B=16, S=2048, D=512)
//
//   k_score2    : p,q dots, 2 frames per warp (MLP ~16)
//   k_scan      : per-batch scan of start flags -> word_start[], n_words[]
//   k_prep_w    : Wh = half(w_comb), k-pair-interleaved layout
//   k_segmean_w : Mh[b,s] = half(mean(frame[st:en]))  (warp/word, MLP=4)
//   k_tgemm_mma : out = Mh @ Wh (+bias, mask), m16n8k16 f16, 4-stage pipeline,
//                 ldmatrix.x4 A-fragments, conflict-free B stride (272)
//
// Fallback SIMT path retained for D != 512.
// ===========================================================================

#define MAX_BS   65536
#define MAX_B    4096
#define Y_ELEMS  ((size_t)1 << 24)   // fallback scratch (fp32)

__device__ float  g_p[MAX_BS];
__device__ float  g_q[MAX_BS];
__device__ float  g_Y[Y_ELEMS];                 // fallback path only
__device__ __half g_Mh[(size_t)MAX_BS * 512];   // segmean, half
__device__ __half g_Wh[256 * 1024];             // w_comb, half, k-pair interleaved
__device__ int    g_wstart[MAX_BS + MAX_B + 1];
__device__ int    g_nw[MAX_B];

// ---------------------------------------------------------------------------
__device__ __forceinline__ uint32_t smem_u32(const void* p) {
    uint32_t a;
    asm("{ .reg .u64 t; cvta.to.shared.u64 t, %1; cvt.u32.u64 %0, t; }"
        : "=r"(a) : "l"(p));
    return a;
}
__device__ __forceinline__ void cp16(uint32_t dst, const void* src) {
    asm volatile("cp.async.cg.shared.global [%0], [%1], 16;" :: "r"(dst), "l"(src));
}
__device__ __forceinline__ void ldsm_x4(uint32_t* r, uint32_t addr) {
    asm volatile("ldmatrix.sync.aligned.m8n8.x4.shared.b16 {%0,%1,%2,%3}, [%4];"
        : "=r"(r[0]), "=r"(r[1]), "=r"(r[2]), "=r"(r[3]) : "r"(addr));
}
__device__ __forceinline__ void mma_f16(float* c, const uint32_t* a, const uint32_t* b) {
    asm volatile(
        "mma.sync.aligned.m16n8k16.row.col.f32.f16.f16.f32 "
        "{%0,%1,%2,%3}, {%4,%5,%6,%7}, {%8,%9}, {%0,%1,%2,%3};"
        : "+f"(c[0]), "+f"(c[1]), "+f"(c[2]), "+f"(c[3])
        : "r"(a[0]), "r"(a[1]), "r"(a[2]), "r"(a[3]), "r"(b[0]), "r"(b[1]));
}

// ---------------------------------------------------------------------------
// Kernel 1: p,q dots; one warp handles TWO frames (doubles loads in flight).
// ---------------------------------------------------------------------------
__global__ void k_score2(const float* __restrict__ x,
                         const float* __restrict__ wscore,
                         int D, int BS)
{
    int wrp  = (blockIdx.x * blockDim.x + threadIdx.x) >> 5;
    int f0   = wrp * 2;
    if (f0 >= BS) return;
    bool has2 = (f0 + 1) < BS;
    int lane = threadIdx.x & 31;
    int n4 = D >> 2;

    const float4* fa = (const float4*)(x + (size_t)f0 * D);
    const float4* fb = (const float4*)(x + (size_t)(f0 + (has2 ? 1 : 0)) * D);
    const float4* w1 = (const float4*)(wscore);
    const float4* w2 = (const float4*)(wscore + D);

    float a = 0.f, b = 0.f, c = 0.f, d = 0.f;
    for (int i = lane; i < n4; i += 32) {
        float4 xv = fa[i];
        float4 yv = fb[i];
        float4 u  = w1[i];
        float4 v  = w2[i];
        a += xv.x * u.x + xv.y * u.y + xv.z * u.z + xv.w * u.w;
        b += xv.x * v.x + xv.y * v.y + xv.z * v.z + xv.w * v.w;
        c += yv.x * u.x + yv.y * u.y + yv.z * u.z + yv.w * u.w;
        d += yv.x * v.x + yv.y * v.y + yv.z * v.z + yv.w * v.w;
    }
    #pragma unroll
    for (int o = 16; o; o >>= 1) {
        a += __shfl_xor_sync(0xffffffffu, a, o);
        b += __shfl_xor_sync(0xffffffffu, b, o);
        c += __shfl_xor_sync(0xffffffffu, c, o);
        d += __shfl_xor_sync(0xffffffffu, d, o);
    }
    if (lane == 0) {
        g_p[f0] = a; g_q[f0] = b;
        if (has2) { g_p[f0 + 1] = c; g_q[f0 + 1] = d; }
    }
}

// ---------------------------------------------------------------------------
// Kernel 2: per-batch scan of start flags -> word boundaries + n_words.
// ---------------------------------------------------------------------------
__global__ void k_scan(const float* __restrict__ bscore_p,
                       int S, float* __restrict__ tail)
{
    const int T = 256;
    int b   = blockIdx.x;
    int tid = threadIdx.x;
    int chunk = (S + T - 1) / T;
    if (chunk > 16) chunk = 16;

    const float* pb = g_p + (size_t)b * S;
    const float* qb = g_q + (size_t)b * S;
    float bsc = *bscore_p;

    int local[16];
    int sum = 0;
    for (int i = 0; i < chunk; i++) {
        int t = tid * chunk + i;
        int st = 0;
        if (t > 0 && t < S) {
            float sc = pb[t - 1] + qb[t] + bsc;
            st = (sc > 0.5f) ? 0 : 1;
        }
        sum += st;
        local[i] = sum;
    }

    int lane = tid & 31, w = tid >> 5;
    int v = sum;
    #pragma unroll
    for (int o = 1; o < 32; o <<= 1) {
        int n = __shfl_up_sync(0xffffffffu, v, o);
        if (lane >= o) v += n;
    }
    __shared__ int wsum[8];
    __shared__ int woff[9];
    if (lane == 31) wsum[w] = v;
    __syncthreads();
    if (tid == 0) {
        int acc = 0;
        for (int i = 0; i < 8; i++) { woff[i] = acc; acc += wsum[i]; }
        woff[8] = acc;
    }
    __syncthreads();

    int excl = woff[w] + (v - sum);
    int* wsb = g_wstart + (size_t)b * (S + 1);
    for (int i = 0; i < chunk; i++) {
        int t = tid * chunk + i;
        if (t < S) {
            int stflag = local[i] - (i ? local[i - 1] : 0);
            int seg = excl + local[i];
            if (t == 0 || stflag) wsb[seg] = t;
        }
    }
    if (tid == 0) {
        int nw = woff[8] + 1;
        wsb[nw] = S;
        g_nw[b] = nw;
        if (tail) tail[b] = (float)nw;
    }
}

// ---------------------------------------------------------------------------
// Kernel W: w_comb -> half, k-pair interleaved: Wh[k>>1][n*2 + (k&1)].
// ---------------------------------------------------------------------------
__global__ void k_prep_w(const float* __restrict__ w)
{
    int idx = blockIdx.x * blockDim.x + threadIdx.x;   // 512*512 elems
    int k = idx >> 9, n = idx & 511;
    g_Wh[(size_t)(k >> 1) * 1024 + (n << 1) + (k & 1)] = __float2half_rn(w[idx]);
}

// ---------------------------------------------------------------------------
// Kernel 3: segment mean -> g_Mh (half). One warp per word, MLP=4 per lane.
// ---------------------------------------------------------------------------
__global__ void k_segmean_w(const float* __restrict__ frame, int S, int BS)
{
    int word = blockIdx.x * 8 + (threadIdx.x >> 5);
    if (word >= BS) return;
    int lane = threadIdx.x & 31;
    int b = word / S, s = word - b * S;
    if (s >= g_nw[b]) return;

    const int* wsb = g_wstart + (size_t)b * (S + 1);
    int st = wsb[s], en = wsb[s + 1];
    float inv = 1.f / (float)(en - st);

    const float4* fb = (const float4*)(frame + ((size_t)b * S) * 512);
    float4 acc[4];
    #pragma unroll
    for (int j = 0; j < 4; j++) acc[j] = make_float4(0.f, 0.f, 0.f, 0.f);

    for (int t = st; t < en; t++) {
        const float4* row = fb + (size_t)t * 128;
        #pragma unroll
        for (int j = 0; j < 4; j++) {
            float4 v = row[lane + j * 32];
            acc[j].x += v.x; acc[j].y += v.y; acc[j].z += v.z; acc[j].w += v.w;
        }
    }
    __half2* mr = (__half2*)(g_Mh + ((size_t)b * S + s) * 512);
    #pragma unroll
    for (int j = 0; j < 4; j++) {
        int i = lane + j * 32;
        mr[i * 2]     = __floats2half2_rn(acc[j].x * inv, acc[j].y * inv);
        mr[i * 2 + 1] = __floats2half2_rn(acc[j].z * inv, acc[j].w * inv);
    }
}

// ---------------------------------------------------------------------------
// Kernel 4: mma.sync f16 GEMM, 4-stage cp.async pipeline, ldmatrix A frags.
// out[BS,512] = Mh[BS,512] @ W[512,512] (+bias, mask).
// Block tile 128x128x32, 8 warps of 64x32.
// Smem A: [128][56] halves (112B stride)   -> conflict-free (direct + ldsm)
// Smem B: [16 pair-rows][272] halves (544B stride) -> conflict-free (t*32B)
// ---------------------------------------------------------------------------
#define MH_ASTRIDE 56
#define MH_ABYTES  (128 * MH_ASTRIDE * 2)       // 14336
#define MH_BSTRIDE 272
#define MH_BBYTES  (16 * MH_BSTRIDE * 2)        // 8704
#define MH_STAGE   (MH_ABYTES + MH_BBYTES)      // 23040
#define MH_NSTAGE  4
#define MH_SMEM    (MH_NSTAGE * MH_STAGE)       // 92160

__device__ __forceinline__ void mh_load(uint32_t base, int stage,
                                        long m0, int n0, int k0, int tid)
{
    uint32_t a_s = base + (uint32_t)stage * MH_STAGE;
    uint32_t b_s = a_s + MH_ABYTES;
    #pragma unroll
    for (int j = 0; j < 2; j++) {                // A: 128 rows x 32 halves (64B)
        int L = tid + 256 * j;
        int row = L >> 2, seg = L & 3;
        cp16(a_s + (uint32_t)row * (MH_ASTRIDE * 2) + (uint32_t)seg * 16,
             g_Mh + (m0 + row) * 512 + k0 + seg * 8);
    }
    #pragma unroll
    for (int j = 0; j < 2; j++) {                // B: 16 pair-rows x 256 halves (512B)
        int L = tid + 256 * j;
        int row = L >> 5, seg = L & 31;
        cp16(b_s + (uint32_t)row * (MH_BSTRIDE * 2) + (uint32_t)seg * 16,
             g_Wh + (size_t)((k0 >> 1) + row) * 1024 + (n0 << 1) + seg * 8);
    }
    asm volatile("cp.async.commit_group;" ::: "memory");
}

__global__ __launch_bounds__(256, 2)
void k_tgemm_mma(const float* __restrict__ bcomb,
                 float* __restrict__ out, int S)
{
    extern __shared__ char smem[];
    uint32_t base = smem_u32(smem);

    int tid  = threadIdx.x;
    long m0 = (long)blockIdx.y * 128;
    int  n0 = blockIdx.x * 128;

    // ---- fully-invalid tile: zero-fill our column strip and exit ----
    {
        int b0 = (int)(m0 / S);
        int s0 = (int)(m0 - (long)b0 * S);
        if (s0 + 128 <= S && s0 >= g_nw[b0]) {
            float4 z = make_float4(0.f, 0.f, 0.f, 0.f);
            #pragma unroll
            for (int j = 0; j < 16; j++) {
                int L = tid + 256 * j;              // 4096 float4 slots
                int row = L >> 5, seg = L & 31;
                *(float4*)(out + (m0 + row) * 512 + n0 + seg * 4) = z;
            }
            return;
        }
    }

    int lane = tid & 31;
    int wid  = tid >> 5;
    int wm   = wid & 1;          // 0/1 -> 64-row half
    int wn   = wid >> 1;         // 0..3 -> 32-col quarter
    int g    = lane >> 2;        // groupID
    int t    = lane & 3;         // threadID_in_group

    // ldmatrix lane address components (A fragment, m16n8k16 row-major)
    int lm_tile   = lane >> 3;                        // 0..3
    int lm_rowoff = (lane & 7) + ((lm_tile & 1) << 3);   // row within 16
    int lm_koff   = (lm_tile >> 1) << 3;              // 0 or 8 halves
    uint32_t lm_lane_b = (uint32_t)((wm * 64 + lm_rowoff) * (MH_ASTRIDE * 2)
                                    + lm_koff * 2);

    float c[4][4][4];
    #pragma unroll
    for (int i = 0; i < 4; i++)
        #pragma unroll
        for (int j = 0; j < 4; j++)
            #pragma unroll
            for (int r = 0; r < 4; r++) c[i][j][r] = 0.f;

    // prologue: 3 stages in flight
    mh_load(base, 0, m0, n0, 0, tid);
    mh_load(base, 1, m0, n0, 32, tid);
    mh_load(base, 2, m0, n0, 64, tid);

    #pragma unroll 1
    for (int ch = 0; ch < 16; ch++) {
        if (ch <= 13)      asm volatile("cp.async.wait_group 2;" ::: "memory");
        else if (ch == 14) asm volatile("cp.async.wait_group 1;" ::: "memory");
        else               asm volatile("cp.async.wait_group 0;" ::: "memory");
        __syncthreads();   // stage ch resident; all warps done with stage (ch-1)

        if (ch + 3 < 16)
            mh_load(base, (ch + 3) & 3, m0, n0, (ch + 3) * 32, tid);

        uint32_t a_stage = base + (uint32_t)(ch & 3) * MH_STAGE;
        uint32_t a_lm    = a_stage + lm_lane_b;
        const __half* Bs = (const __half*)(smem + (size_t)(ch & 3) * MH_STAGE + MH_ABYTES);

        #pragma unroll
        for (int kk = 0; kk < 32; kk += 16) {
            uint32_t af[4][4];
            #pragma unroll
            for (int mt = 0; mt < 4; mt++)
                ldsm_x4(af[mt], a_lm + (uint32_t)(mt * 16 * (MH_ASTRIDE * 2) + kk * 2));

            uint32_t bf[4][2];
            #pragma unroll
            for (int nt = 0; nt < 4; nt++) {
                int col = wn * 32 + nt * 8 + g;
                const __half* bp = Bs + (size_t)((kk >> 1) + t) * MH_BSTRIDE + col * 2;
                bf[nt][0] = *(const uint32_t*)(bp);
                bf[nt][1] = *(const uint32_t*)(bp + 4 * MH_BSTRIDE);
            }
            #pragma unroll
            for (int mt = 0; mt < 4; mt++)
                #pragma unroll
                for (int nt = 0; nt < 4; nt++)
                    mma_f16(c[mt][nt], af[mt], bf[nt]);
        }
    }

    // epilogue: bias + validity mask, float2 stores
    #pragma unroll
    for (int mt = 0; mt < 4; mt++) {
        #pragma unroll
        for (int half = 0; half < 2; half++) {
            long grow = m0 + wm * 64 + mt * 16 + g + half * 8;
            int b = (int)(grow / S);
            int s = (int)(grow - (long)b * S);
            bool valid = s < g_nw[b];
            float* orow = out + grow * 512 + n0;
            #pragma unroll
            for (int nt = 0; nt < 4; nt++) {
                int col = wn * 32 + nt * 8 + t * 2;
                float2 v;
                if (valid) {
                    v.x = c[mt][nt][half * 2 + 0] + bcomb[n0 + col];
                    v.y = c[mt][nt][half * 2 + 1] + bcomb[n0 + col + 1];
                } else {
                    v.x = 0.f; v.y = 0.f;
                }
                *(float2*)(orow + col) = v;
            }
        }
    }
}

// ---------------------------------------------------------------------------
// Fallback SIMT path (D != 512): fp32 SGEMM + segment-average.
// ---------------------------------------------------------------------------
#define BM 128
#define BN 128
#define BK 8
__global__ __launch_bounds__(256, 2)
void k_gemm(const float* __restrict__ A, const float* __restrict__ Wm,
            int M, int N, int K)
{
    __shared__ float As[2][BK][BM];
    __shared__ float Bs[2][BK][BN];
    int bx = blockIdx.x, by = blockIdx.y;
    int tid = threadIdx.x;
    int tx = tid & 15, ty = tid >> 4;
    int arow = tid >> 1, acol = (tid & 1) * 4;
    int brow = tid >> 5, bcol = (tid & 31) * 4;
    const float* Ap = A + ((size_t)(by * BM + arow)) * K + acol;
    const float* Bp = Wm + (size_t)brow * N + bx * BN + bcol;

    float acc[8][8];
    #pragma unroll
    for (int i = 0; i < 8; i++)
        #pragma unroll
        for (int j = 0; j < 8; j++) acc[i][j] = 0.f;

    float4 a4 = *(const float4*)Ap;
    float4 b4 = *(const float4*)Bp;
    As[0][acol + 0][arow] = a4.x; As[0][acol + 1][arow] = a4.y;
    As[0][acol + 2][arow] = a4.z; As[0][acol + 3][arow] = a4.w;
    *(float4*)&Bs[0][brow][bcol] = b4;
    __syncthreads();

    int buf = 0;
    for (int k0 = 0; k0 < K; k0 += BK) {
        bool more = (k0 + BK) < K;
        float4 na, nb;
        if (more) {
            na = *(const float4*)(Ap + (k0 + BK));
            nb = *(const float4*)(Bp + (size_t)(k0 + BK) * N);
        }
        #pragma unroll
        for (int k = 0; k < BK; k++) {
            float ra[8], rb[8];
            *(float4*)(ra + 0) = *(float4*)&As[buf][k][ty * 4];
            *(float4*)(ra + 4) = *(float4*)&As[buf][k][64 + ty * 4];
            *(float4*)(rb + 0) = *(float4*)&Bs[buf][k][tx * 4];
            *(float4*)(rb + 4) = *(float4*)&Bs[buf][k][64 + tx * 4];
            #pragma unroll
            for (int i = 0; i < 8; i++)
                #pragma unroll
                for (int j = 0; j < 8; j++)
                    acc[i][j] = fmaf(ra[i], rb[j], acc[i][j]);
        }
        if (more) {
            int nxt = buf ^ 1;
            As[nxt][acol + 0][arow] = na.x; As[nxt][acol + 1][arow] = na.y;
            As[nxt][acol + 2][arow] = na.z; As[nxt][acol + 3][arow] = na.w;
            *(float4*)&Bs[nxt][brow][bcol] = nb;
            __syncthreads();
            buf = nxt;
        }
    }
    #pragma unroll
    for (int i = 0; i < 8; i++) {
        int r = by * BM + ((i < 4) ? (ty * 4 + i) : (64 + ty * 4 + i - 4));
        float* crow = g_Y + (size_t)r * N + bx * BN;
        *(float4*)(crow + tx * 4)      = make_float4(acc[i][0], acc[i][1], acc[i][2], acc[i][3]);
        *(float4*)(crow + 64 + tx * 4) = make_float4(acc[i][4], acc[i][5], acc[i][6], acc[i][7]);
    }
}

__global__ void k_avg(const float* __restrict__ bcomb,
                      float* __restrict__ out, int S, int D)
{
    int b = blockIdx.y, s = blockIdx.x;
    int n4 = D >> 2;
    float4* orow = (float4*)(out + ((size_t)b * S + s) * D);
    int nw = g_nw[b];
    if (s >= nw) {
        for (int i = threadIdx.x; i < n4; i += blockDim.x)
            orow[i] = make_float4(0.f, 0.f, 0.f, 0.f);
        return;
    }
    const int* wsb = g_wstart + (size_t)b * (S + 1);
    int st = wsb[s], en = wsb[s + 1];
    float inv = 1.f / (float)(en - st);
    const float4* ybase = (const float4*)(g_Y + ((size_t)b * S) * D);
    const float4* bc4 = (const float4*)bcomb;
    for (int i = threadIdx.x; i < n4; i += blockDim.x) {
        float4 acc = make_float4(0.f, 0.f, 0.f, 0.f);
        for (int tt = st; tt < en; tt++) {
            float4 v = ybase[(size_t)tt * n4 + i];
            acc.x += v.x; acc.y += v.y; acc.z += v.z; acc.w += v.w;
        }
        float4 bb = bc4[i];
        orow[i] = make_float4(acc.x * inv + bb.x, acc.y * inv + bb.y,
                              acc.z * inv + bb.z, acc.w * inv + bb.w);
    }
}

// ---------------------------------------------------------------------------
extern "C" void kernel_launch(void* const* d_in, const int* in_sizes, int n_in,
                              void* d_out, int out_size)
{
    const float* frame  = (const float*)d_in[0];
    const float* wscore = (const float*)d_in[1];
    const float* bscore = (const float*)d_in[2];
    const float* wcomb  = (const float*)d_in[3];
    const float* bcomb  = (const float*)d_in[4];
    float* out = (float*)d_out;

    int D   = in_sizes[1] / 2;
    long total = in_sizes[0];
    int BS  = (int)(total / D);

    int B = out_size - (int)total;
    if (B <= 0 || B > MAX_B || (BS % B) != 0) {
        B = 16;
        while (B > 1 && (BS % B) != 0) B >>= 1;
    }
    int S = BS / B;
    float* tail = (out_size == (int)total + B) ? (out + total) : nullptr;

    // 1) per-frame score dots (2 frames per warp)
    {
        int warps = (BS + 1) / 2;
        int blocks = (warps + 7) / 8;
        k_score2<<<blocks, 256>>>(frame, wscore, D, BS);
    }
    // 2) per-batch scan
    k_scan<<<B, 256>>>(bscore, S, tail);

    if (D == 512 && (BS % 128) == 0) {
        // --- tensor path (mma.sync m16n8k16 f16, 4-stage, ldmatrix) ---
        k_prep_w<<<512 * 512 / 256, 256>>>(wcomb);
        k_segmean_w<<<(BS + 7) / 8, 256>>>(frame, S, BS);
        static int smem_set = 0;
        if (!smem_set) {
            cudaFuncSetAttribute(k_tgemm_mma,
                                 cudaFuncAttributeMaxDynamicSharedMemorySize, MH_SMEM);
            smem_set = 1;
        }
        dim3 grid(512 / 128, BS / 128);
        k_tgemm_mma<<<grid, 256, MH_SMEM>>>(bcomb, out, S);
    } else {
        // --- fallback SIMT path ---
        dim3 grid(D / BN, BS / BM);
        k_gemm<<<grid, 256>>>(frame, wcomb, BS, D, D);
        dim3 agrid(S, B);
        k_avg<<<agrid, 128>>>(bcomb, out, S, D);
    }
}

// round 9
// speedup vs baseline: 4.0934x; 1.0349x over previous
#include <cuda_runtime.h>
#include <cuda_bf16.h>
#include <cuda_fp16.h>
#include <cstdint>

// ===========================================================================
// WordSpeechContinuousFusion  (B=16, S=2048, D=512)
//
//   k_score4p   : p,q dots, 4 frames per warp (MLP ~24) + tail blocks convert
//                 w_comb -> g_Wh (k-pair interleaved half)   [merged launch]
//   k_scan      : per-batch scan of start flags -> word_start[], n_words[]
//   k_segmean_w2: Mh[b,s] = half(mean(frame[st:en])), 2 words/warp interleaved
//   k_tgemm_mma : out = Mh @ Wh (+bias, mask), m16n8k16 f16, 4-stage pipeline,
//                 ldmatrix.x4 A-fragments, conflict-free B stride (272)
//
// Fallback SIMT path retained for D != 512.
// ===========================================================================

#define MAX_BS   65536
#define MAX_B    4096
#define Y_ELEMS  ((size_t)1 << 24)   // fallback scratch (fp32)

__device__ float  g_p[MAX_BS];
__device__ float  g_q[MAX_BS];
__device__ float  g_Y[Y_ELEMS];                 // fallback path only
__device__ __half g_Mh[(size_t)MAX_BS * 512];   // segmean, half
__device__ __half g_Wh[256 * 1024];             // w_comb, half, k-pair interleaved
__device__ int    g_wstart[MAX_BS + MAX_B + 1];
__device__ int    g_nw[MAX_B];

// ---------------------------------------------------------------------------
__device__ __forceinline__ uint32_t smem_u32(const void* p) {
    uint32_t a;
    asm("{ .reg .u64 t; cvta.to.shared.u64 t, %1; cvt.u32.u64 %0, t; }"
        : "=r"(a) : "l"(p));
    return a;
}
__device__ __forceinline__ void cp16(uint32_t dst, const void* src) {
    asm volatile("cp.async.cg.shared.global [%0], [%1], 16;" :: "r"(dst), "l"(src));
}
__device__ __forceinline__ void ldsm_x4(uint32_t* r, uint32_t addr) {
    asm volatile("ldmatrix.sync.aligned.m8n8.x4.shared.b16 {%0,%1,%2,%3}, [%4];"
        : "=r"(r[0]), "=r"(r[1]), "=r"(r[2]), "=r"(r[3]) : "r"(addr));
}
__device__ __forceinline__ void mma_f16(float* c, const uint32_t* a, const uint32_t* b) {
    asm volatile(
        "mma.sync.aligned.m16n8k16.row.col.f32.f16.f16.f32 "
        "{%0,%1,%2,%3}, {%4,%5,%6,%7}, {%8,%9}, {%0,%1,%2,%3};"
        : "+f"(c[0]), "+f"(c[1]), "+f"(c[2]), "+f"(c[3])
        : "r"(a[0]), "r"(a[1]), "r"(a[2]), "r"(a[3]), "r"(b[0]), "r"(b[1]));
}

// ---------------------------------------------------------------------------
// Kernel 1: 4 frames per warp score dots; tail blocks convert w_comb -> g_Wh.
// ---------------------------------------------------------------------------
__global__ void k_score4p(const float* __restrict__ x,
                          const float* __restrict__ wscore,
                          const float* __restrict__ wcomb,
                          int D, int BS, int score_blocks, int do_prep)
{
    if ((int)blockIdx.x >= score_blocks) {
        if (!do_prep) return;
        // W prep: 256 tail blocks x 256 threads x 4 elems = 512*512
        int base = ((int)blockIdx.x - score_blocks) * 1024 + threadIdx.x * 4;
        if (base + 3 < 512 * 512) {
            float4 v = *(const float4*)(wcomb + base);
            int k = base >> 9, n = base & 511;
            __half* dst = g_Wh + (size_t)(k >> 1) * 1024 + (n << 1) + (k & 1);
            dst[0] = __float2half_rn(v.x);
            dst[2] = __float2half_rn(v.y);
            dst[4] = __float2half_rn(v.z);
            dst[6] = __float2half_rn(v.w);
        }
        return;
    }

    int wrp  = blockIdx.x * 8 + (threadIdx.x >> 5);
    int f0   = wrp * 4;
    if (f0 >= BS) return;
    int lane = threadIdx.x & 31;
    int n4 = D >> 2;

    const float4* w1 = (const float4*)(wscore);
    const float4* w2 = (const float4*)(wscore + D);
    const float4* fr[4];
    bool has[4];
    #pragma unroll
    for (int j = 0; j < 4; j++) {
        has[j] = (f0 + j) < BS;
        fr[j] = (const float4*)(x + (size_t)(f0 + (has[j] ? j : 0)) * D);
    }

    float pa[4] = {0.f, 0.f, 0.f, 0.f};
    float qa[4] = {0.f, 0.f, 0.f, 0.f};
    for (int i = lane; i < n4; i += 32) {
        float4 u = w1[i];
        float4 v = w2[i];
        #pragma unroll
        for (int j = 0; j < 4; j++) {
            float4 xv = fr[j][i];
            pa[j] += xv.x * u.x + xv.y * u.y + xv.z * u.z + xv.w * u.w;
            qa[j] += xv.x * v.x + xv.y * v.y + xv.z * v.z + xv.w * v.w;
        }
    }
    #pragma unroll
    for (int o = 16; o; o >>= 1) {
        #pragma unroll
        for (int j = 0; j < 4; j++) {
            pa[j] += __shfl_xor_sync(0xffffffffu, pa[j], o);
            qa[j] += __shfl_xor_sync(0xffffffffu, qa[j], o);
        }
    }
    if (lane == 0) {
        #pragma unroll
        for (int j = 0; j < 4; j++)
            if (has[j]) { g_p[f0 + j] = pa[j]; g_q[f0 + j] = qa[j]; }
    }
}

// ---------------------------------------------------------------------------
// Kernel 2: per-batch scan of start flags -> word boundaries + n_words.
// ---------------------------------------------------------------------------
__global__ void k_scan(const float* __restrict__ bscore_p,
                       int S, float* __restrict__ tail)
{
    const int T = 256;
    int b   = blockIdx.x;
    int tid = threadIdx.x;
    int chunk = (S + T - 1) / T;
    if (chunk > 16) chunk = 16;

    const float* pb = g_p + (size_t)b * S;
    const float* qb = g_q + (size_t)b * S;
    float bsc = *bscore_p;

    int local[16];
    int sum = 0;
    for (int i = 0; i < chunk; i++) {
        int t = tid * chunk + i;
        int st = 0;
        if (t > 0 && t < S) {
            float sc = pb[t - 1] + qb[t] + bsc;
            st = (sc > 0.5f) ? 0 : 1;
        }
        sum += st;
        local[i] = sum;
    }

    int lane = tid & 31, w = tid >> 5;
    int v = sum;
    #pragma unroll
    for (int o = 1; o < 32; o <<= 1) {
        int n = __shfl_up_sync(0xffffffffu, v, o);
        if (lane >= o) v += n;
    }
    __shared__ int wsum[8];
    __shared__ int woff[9];
    if (lane == 31) wsum[w] = v;
    __syncthreads();
    if (tid == 0) {
        int acc = 0;
        for (int i = 0; i < 8; i++) { woff[i] = acc; acc += wsum[i]; }
        woff[8] = acc;
    }
    __syncthreads();

    int excl = woff[w] + (v - sum);
    int* wsb = g_wstart + (size_t)b * (S + 1);
    for (int i = 0; i < chunk; i++) {
        int t = tid * chunk + i;
        if (t < S) {
            int stflag = local[i] - (i ? local[i - 1] : 0);
            int seg = excl + local[i];
            if (t == 0 || stflag) wsb[seg] = t;
        }
    }
    if (tid == 0) {
        int nw = woff[8] + 1;
        wsb[nw] = S;
        g_nw[b] = nw;
        if (tail) tail[b] = (float)nw;
    }
}

// ---------------------------------------------------------------------------
// Kernel 3: segment mean -> g_Mh (half). TWO words per warp, interleaved
// accumulation (MLP ~8). Word ranges are warp-uniform -> no divergence.
// ---------------------------------------------------------------------------
__global__ void k_segmean_w2(const float* __restrict__ frame, int S, int BS)
{
    int w0 = (blockIdx.x * 8 + (threadIdx.x >> 5)) * 2;
    if (w0 >= BS) return;
    int w1 = w0 + 1;
    bool has1 = w1 < BS;
    int lane = threadIdx.x & 31;

    int b0 = w0 / S, s0 = w0 - b0 * S;
    int b1 = has1 ? (w1 / S) : b0;
    int s1 = has1 ? (w1 - b1 * S) : 0;

    bool v0 = s0 < g_nw[b0];
    bool v1 = has1 && (s1 < g_nw[b1]);

    int st0 = 0, en0 = 0, st1 = 0, en1 = 0;
    if (v0) {
        const int* wsb = g_wstart + (size_t)b0 * (S + 1);
        st0 = wsb[s0]; en0 = wsb[s0 + 1];
    }
    if (v1) {
        const int* wsb = g_wstart + (size_t)b1 * (S + 1);
        st1 = wsb[s1]; en1 = wsb[s1 + 1];
    }
    int len0 = en0 - st0, len1 = en1 - st1;
    int L = len0 > len1 ? len0 : len1;
    if (L == 0) return;

    const float4* f0 = (const float4*)(frame + ((size_t)b0 * S) * 512);
    const float4* f1 = (const float4*)(frame + ((size_t)b1 * S) * 512);

    float4 a0[4], a1[4];
    #pragma unroll
    for (int j = 0; j < 4; j++) {
        a0[j] = make_float4(0.f, 0.f, 0.f, 0.f);
        a1[j] = make_float4(0.f, 0.f, 0.f, 0.f);
    }

    for (int i = 0; i < L; i++) {
        if (i < len0) {
            const float4* row = f0 + (size_t)(st0 + i) * 128;
            #pragma unroll
            for (int j = 0; j < 4; j++) {
                float4 v = row[lane + j * 32];
                a0[j].x += v.x; a0[j].y += v.y; a0[j].z += v.z; a0[j].w += v.w;
            }
        }
        if (i < len1) {
            const float4* row = f1 + (size_t)(st1 + i) * 128;
            #pragma unroll
            for (int j = 0; j < 4; j++) {
                float4 v = row[lane + j * 32];
                a1[j].x += v.x; a1[j].y += v.y; a1[j].z += v.z; a1[j].w += v.w;
            }
        }
    }

    if (v0) {
        float inv = 1.f / (float)len0;
        __half2* mr = (__half2*)(g_Mh + (size_t)w0 * 512);
        #pragma unroll
        for (int j = 0; j < 4; j++) {
            int i = lane + j * 32;
            mr[i * 2]     = __floats2half2_rn(a0[j].x * inv, a0[j].y * inv);
            mr[i * 2 + 1] = __floats2half2_rn(a0[j].z * inv, a0[j].w * inv);
        }
    }
    if (v1) {
        float inv = 1.f / (float)len1;
        __half2* mr = (__half2*)(g_Mh + (size_t)w1 * 512);
        #pragma unroll
        for (int j = 0; j < 4; j++) {
            int i = lane + j * 32;
            mr[i * 2]     = __floats2half2_rn(a1[j].x * inv, a1[j].y * inv);
            mr[i * 2 + 1] = __floats2half2_rn(a1[j].z * inv, a1[j].w * inv);
        }
    }
}

// ---------------------------------------------------------------------------
// Kernel 4: mma.sync f16 GEMM, 4-stage cp.async pipeline, ldmatrix A frags.
// out[BS,512] = Mh[BS,512] @ W[512,512] (+bias, mask).  (unchanged from R8)
// ---------------------------------------------------------------------------
#define MH_ASTRIDE 56
#define MH_ABYTES  (128 * MH_ASTRIDE * 2)       // 14336
#define MH_BSTRIDE 272
#define MH_BBYTES  (16 * MH_BSTRIDE * 2)        // 8704
#define MH_STAGE   (MH_ABYTES + MH_BBYTES)      // 23040
#define MH_NSTAGE  4
#define MH_SMEM    (MH_NSTAGE * MH_STAGE)       // 92160

__device__ __forceinline__ void mh_load(uint32_t base, int stage,
                                        long m0, int n0, int k0, int tid)
{
    uint32_t a_s = base + (uint32_t)stage * MH_STAGE;
    uint32_t b_s = a_s + MH_ABYTES;
    #pragma unroll
    for (int j = 0; j < 2; j++) {                // A: 128 rows x 32 halves (64B)
        int L = tid + 256 * j;
        int row = L >> 2, seg = L & 3;
        cp16(a_s + (uint32_t)row * (MH_ASTRIDE * 2) + (uint32_t)seg * 16,
             g_Mh + (m0 + row) * 512 + k0 + seg * 8);
    }
    #pragma unroll
    for (int j = 0; j < 2; j++) {                // B: 16 pair-rows x 256 halves (512B)
        int L = tid + 256 * j;
        int row = L >> 5, seg = L & 31;
        cp16(b_s + (uint32_t)row * (MH_BSTRIDE * 2) + (uint32_t)seg * 16,
             g_Wh + (size_t)((k0 >> 1) + row) * 1024 + (n0 << 1) + seg * 8);
    }
    asm volatile("cp.async.commit_group;" ::: "memory");
}

__global__ __launch_bounds__(256, 2)
void k_tgemm_mma(const float* __restrict__ bcomb,
                 float* __restrict__ out, int S)
{
    extern __shared__ char smem[];
    uint32_t base = smem_u32(smem);

    int tid  = threadIdx.x;
    long m0 = (long)blockIdx.y * 128;
    int  n0 = blockIdx.x * 128;

    // ---- fully-invalid tile: zero-fill our column strip and exit ----
    {
        int b0 = (int)(m0 / S);
        int s0 = (int)(m0 - (long)b0 * S);
        if (s0 + 128 <= S && s0 >= g_nw[b0]) {
            float4 z = make_float4(0.f, 0.f, 0.f, 0.f);
            #pragma unroll
            for (int j = 0; j < 16; j++) {
                int L = tid + 256 * j;              // 4096 float4 slots
                int row = L >> 5, seg = L & 31;
                *(float4*)(out + (m0 + row) * 512 + n0 + seg * 4) = z;
            }
            return;
        }
    }

    int lane = tid & 31;
    int wid  = tid >> 5;
    int wm   = wid & 1;          // 0/1 -> 64-row half
    int wn   = wid >> 1;         // 0..3 -> 32-col quarter
    int g    = lane >> 2;        // groupID
    int t    = lane & 3;         // threadID_in_group

    // ldmatrix lane address components (A fragment, m16n8k16 row-major)
    int lm_tile   = lane >> 3;                        // 0..3
    int lm_rowoff = (lane & 7) + ((lm_tile & 1) << 3);   // row within 16
    int lm_koff   = (lm_tile >> 1) << 3;              // 0 or 8 halves
    uint32_t lm_lane_b = (uint32_t)((wm * 64 + lm_rowoff) * (MH_ASTRIDE * 2)
                                    + lm_koff * 2);

    float c[4][4][4];
    #pragma unroll
    for (int i = 0; i < 4; i++)
        #pragma unroll
        for (int j = 0; j < 4; j++)
            #pragma unroll
            for (int r = 0; r < 4; r++) c[i][j][r] = 0.f;

    // prologue: 3 stages in flight
    mh_load(base, 0, m0, n0, 0, tid);
    mh_load(base, 1, m0, n0, 32, tid);
    mh_load(base, 2, m0, n0, 64, tid);

    #pragma unroll 1
    for (int ch = 0; ch < 16; ch++) {
        if (ch <= 13)      asm volatile("cp.async.wait_group 2;" ::: "memory");
        else if (ch == 14) asm volatile("cp.async.wait_group 1;" ::: "memory");
        else               asm volatile("cp.async.wait_group 0;" ::: "memory");
        __syncthreads();   // stage ch resident; all warps done with stage (ch-1)

        if (ch + 3 < 16)
            mh_load(base, (ch + 3) & 3, m0, n0, (ch + 3) * 32, tid);

        uint32_t a_stage = base + (uint32_t)(ch & 3) * MH_STAGE;
        uint32_t a_lm    = a_stage + lm_lane_b;
        const __half* Bs = (const __half*)(smem + (size_t)(ch & 3) * MH_STAGE + MH_ABYTES);

        #pragma unroll
        for (int kk = 0; kk < 32; kk += 16) {
            uint32_t af[4][4];
            #pragma unroll
            for (int mt = 0; mt < 4; mt++)
                ldsm_x4(af[mt], a_lm + (uint32_t)(mt * 16 * (MH_ASTRIDE * 2) + kk * 2));

            uint32_t bf[4][2];
            #pragma unroll
            for (int nt = 0; nt < 4; nt++) {
                int col = wn * 32 + nt * 8 + g;
                const __half* bp = Bs + (size_t)((kk >> 1) + t) * MH_BSTRIDE + col * 2;
                bf[nt][0] = *(const uint32_t*)(bp);
                bf[nt][1] = *(const uint32_t*)(bp + 4 * MH_BSTRIDE);
            }
            #pragma unroll
            for (int mt = 0; mt < 4; mt++)
                #pragma unroll
                for (int nt = 0; nt < 4; nt++)
                    mma_f16(c[mt][nt], af[mt], bf[nt]);
        }
    }

    // epilogue: bias + validity mask, float2 stores
    #pragma unroll
    for (int mt = 0; mt < 4; mt++) {
        #pragma unroll
        for (int half = 0; half < 2; half++) {
            long grow = m0 + wm * 64 + mt * 16 + g + half * 8;
            int b = (int)(grow / S);
            int s = (int)(grow - (long)b * S);
            bool valid = s < g_nw[b];
            float* orow = out + grow * 512 + n0;
            #pragma unroll
            for (int nt = 0; nt < 4; nt++) {
                int col = wn * 32 + nt * 8 + t * 2;
                float2 v;
                if (valid) {
                    v.x = c[mt][nt][half * 2 + 0] + bcomb[n0 + col];
                    v.y = c[mt][nt][half * 2 + 1] + bcomb[n0 + col + 1];
                } else {
                    v.x = 0.f; v.y = 0.f;
                }
                *(float2*)(orow + col) = v;
            }
        }
    }
}

// ---------------------------------------------------------------------------
// Fallback SIMT path (D != 512): fp32 SGEMM + segment-average.
// ---------------------------------------------------------------------------
#define BM 128
#define BN 128
#define BK 8
__global__ __launch_bounds__(256, 2)
void k_gemm(const float* __restrict__ A, const float* __restrict__ Wm,
            int M, int N, int K)
{
    __shared__ float As[2][BK][BM];
    __shared__ float Bs[2][BK][BN];
    int bx = blockIdx.x, by = blockIdx.y;
    int tid = threadIdx.x;
    int tx = tid & 15, ty = tid >> 4;
    int arow = tid >> 1, acol = (tid & 1) * 4;
    int brow = tid >> 5, bcol = (tid & 31) * 4;
    const float* Ap = A + ((size_t)(by * BM + arow)) * K + acol;
    const float* Bp = Wm + (size_t)brow * N + bx * BN + bcol;

    float acc[8][8];
    #pragma unroll
    for (int i = 0; i < 8; i++)
        #pragma unroll
        for (int j = 0; j < 8; j++) acc[i][j] = 0.f;

    float4 a4 = *(const float4*)Ap;
    float4 b4 = *(const float4*)Bp;
    As[0][acol + 0][arow] = a4.x; As[0][acol + 1][arow] = a4.y;
    As[0][acol + 2][arow] = a4.z; As[0][acol + 3][arow] = a4.w;
    *(float4*)&Bs[0][brow][bcol] = b4;
    __syncthreads();

    int buf = 0;
    for (int k0 = 0; k0 < K; k0 += BK) {
        bool more = (k0 + BK) < K;
        float4 na, nb;
        if (more) {
            na = *(const float4*)(Ap + (k0 + BK));
            nb = *(const float4*)(Bp + (size_t)(k0 + BK) * N);
        }
        #pragma unroll
        for (int k = 0; k < BK; k++) {
            float ra[8], rb[8];
            *(float4*)(ra + 0) = *(float4*)&As[buf][k][ty * 4];
            *(float4*)(ra + 4) = *(float4*)&As[buf][k][64 + ty * 4];
            *(float4*)(rb + 0) = *(float4*)&Bs[buf][k][tx * 4];
            *(float4*)(rb + 4) = *(float4*)&Bs[buf][k][64 + tx * 4];
            #pragma unroll
            for (int i = 0; i < 8; i++)
                #pragma unroll
                for (int j = 0; j < 8; j++)
                    acc[i][j] = fmaf(ra[i], rb[j], acc[i][j]);
        }
        if (more) {
            int nxt = buf ^ 1;
            As[nxt][acol + 0][arow] = na.x; As[nxt][acol + 1][arow] = na.y;
            As[nxt][acol + 2][arow] = na.z; As[nxt][acol + 3][arow] = na.w;
            *(float4*)&Bs[nxt][brow][bcol] = nb;
            __syncthreads();
            buf = nxt;
        }
    }
    #pragma unroll
    for (int i = 0; i < 8; i++) {
        int r = by * BM + ((i < 4) ? (ty * 4 + i) : (64 + ty * 4 + i - 4));
        float* crow = g_Y + (size_t)r * N + bx * BN;
        *(float4*)(crow + tx * 4)      = make_float4(acc[i][0], acc[i][1], acc[i][2], acc[i][3]);
        *(float4*)(crow + 64 + tx * 4) = make_float4(acc[i][4], acc[i][5], acc[i][6], acc[i][7]);
    }
}

__global__ void k_avg(const float* __restrict__ bcomb,
                      float* __restrict__ out, int S, int D)
{
    int b = blockIdx.y, s = blockIdx.x;
    int n4 = D >> 2;
    float4* orow = (float4*)(out + ((size_t)b * S + s) * D);
    int nw = g_nw[b];
    if (s >= nw) {
        for (int i = threadIdx.x; i < n4; i += blockDim.x)
            orow[i] = make_float4(0.f, 0.f, 0.f, 0.f);
        return;
    }
    const int* wsb = g_wstart + (size_t)b * (S + 1);
    int st = wsb[s], en = wsb[s + 1];
    float inv = 1.f / (float)(en - st);
    const float4* ybase = (const float4*)(g_Y + ((size_t)b * S) * D);
    const float4* bc4 = (const float4*)bcomb;
    for (int i = threadIdx.x; i < n4; i += blockDim.x) {
        float4 acc = make_float4(0.f, 0.f, 0.f, 0.f);
        for (int tt = st; tt < en; tt++) {
            float4 v = ybase[(size_t)tt * n4 + i];
            acc.x += v.x; acc.y += v.y; acc.z += v.z; acc.w += v.w;
        }
        float4 bb = bc4[i];
        orow[i] = make_float4(acc.x * inv + bb.x, acc.y * inv + bb.y,
                              acc.z * inv + bb.z, acc.w * inv + bb.w);
    }
}

// ---------------------------------------------------------------------------
extern "C" void kernel_launch(void* const* d_in, const int* in_sizes, int n_in,
                              void* d_out, int out_size)
{
    const float* frame  = (const float*)d_in[0];
    const float* wscore = (const float*)d_in[1];
    const float* bscore = (const float*)d_in[2];
    const float* wcomb  = (const float*)d_in[3];
    const float* bcomb  = (const float*)d_in[4];
    float* out = (float*)d_out;

    int D   = in_sizes[1] / 2;
    long total = in_sizes[0];
    int BS  = (int)(total / D);

    int B = out_size - (int)total;
    if (B <= 0 || B > MAX_B || (BS % B) != 0) {
        B = 16;
        while (B > 1 && (BS % B) != 0) B >>= 1;
    }
    int S = BS / B;
    float* tail = (out_size == (int)total + B) ? (out + total) : nullptr;

    bool tpath = (D == 512 && (BS % 128) == 0);

    // 1) score dots (4 frames/warp) + merged W-prep tail blocks
    {
        int score_blocks = (BS + 31) / 32;
        int prep_blocks  = tpath ? 256 : 0;
        k_score4p<<<score_blocks + prep_blocks, 256>>>(
            frame, wscore, wcomb, D, BS, score_blocks, tpath ? 1 : 0);
    }
    // 2) per-batch scan
    k_scan<<<B, 256>>>(bscore, S, tail);

    if (tpath) {
        // --- tensor path (mma.sync m16n8k16 f16, 4-stage, ldmatrix) ---
        k_segmean_w2<<<(BS / 2 + 7) / 8, 256>>>(frame, S, BS);
        static int smem_set = 0;
        if (!smem_set) {
            cudaFuncSetAttribute(k_tgemm_mma,
                                 cudaFuncAttributeMaxDynamicSharedMemorySize, MH_SMEM);
            smem_set = 1;
        }
        dim3 grid(512 / 128, BS / 128);
        k_tgemm_mma<<<grid, 256, MH_SMEM>>>(bcomb, out, S);
    } else {
        // --- fallback SIMT path ---
        dim3 grid(D / BN, BS / BM);
        k_gemm<<<grid, 256>>>(frame, wcomb, BS, D, D);
        dim3 agrid(S, B);
        k_avg<<<agrid, 128>>>(bcomb, out, S, D);
    }
}

// round 10
// speedup vs baseline: 4.0961x; 1.0007x over previous
#include <cuda_runtime.h>
#include <cuda_bf16.h>
#include <cuda_fp16.h>
#include <cstdint>

// ===========================================================================
// WordSpeechContinuousFusion  (B=16, S=2048, D=512)
//
//   k_score4p   : p,q dots, 4 frames/warp + tail blocks convert w_comb -> half
//   k_scan      : per-batch scan of start flags -> word_start[], n_words[]
//   k_segmean_w2: Mh[b,s] = half(mean(frame[st:en])), 2 words/warp interleaved
//   k_tgemm_mma : out = Mh @ Wh (+bias, mask), m16n8k16 f16, 4-stage cp.async,
//                 ldmatrix.x4 A frags + ldmatrix.x4.trans B frags,
//                 explicit 2-set fragment pipelining per 32-K chunk.
//
// Fallback SIMT path retained for D != 512.
// ===========================================================================

#define MAX_BS   65536
#define MAX_B    4096
#define Y_ELEMS  ((size_t)1 << 24)   // fallback scratch (fp32)

__device__ float  g_p[MAX_BS];
__device__ float  g_q[MAX_BS];
__device__ float  g_Y[Y_ELEMS];                 // fallback path only
__device__ __half g_Mh[(size_t)MAX_BS * 512];   // segmean, half
__device__ __half g_Wh[512 * 512];              // w_comb, half, row-major [k][n]
__device__ int    g_wstart[MAX_BS + MAX_B + 1];
__device__ int    g_nw[MAX_B];

// ---------------------------------------------------------------------------
__device__ __forceinline__ uint32_t smem_u32(const void* p) {
    uint32_t a;
    asm("{ .reg .u64 t; cvta.to.shared.u64 t, %1; cvt.u32.u64 %0, t; }"
        : "=r"(a) : "l"(p));
    return a;
}
__device__ __forceinline__ void cp16(uint32_t dst, const void* src) {
    asm volatile("cp.async.cg.shared.global [%0], [%1], 16;" :: "r"(dst), "l"(src));
}
__device__ __forceinline__ void ldsm_x4(uint32_t* r, uint32_t addr) {
    asm volatile("ldmatrix.sync.aligned.m8n8.x4.shared.b16 {%0,%1,%2,%3}, [%4];"
        : "=r"(r[0]), "=r"(r[1]), "=r"(r[2]), "=r"(r[3]) : "r"(addr));
}
__device__ __forceinline__ void ldsm_x4_t(uint32_t* r, uint32_t addr) {
    asm volatile("ldmatrix.sync.aligned.m8n8.x4.trans.shared.b16 {%0,%1,%2,%3}, [%4];"
        : "=r"(r[0]), "=r"(r[1]), "=r"(r[2]), "=r"(r[3]) : "r"(addr));
}
__device__ __forceinline__ void mma_f16(float* c, const uint32_t* a,
                                        uint32_t b0, uint32_t b1) {
    asm volatile(
        "mma.sync.aligned.m16n8k16.row.col.f32.f16.f16.f32 "
        "{%0,%1,%2,%3}, {%4,%5,%6,%7}, {%8,%9}, {%0,%1,%2,%3};"
        : "+f"(c[0]), "+f"(c[1]), "+f"(c[2]), "+f"(c[3])
        : "r"(a[0]), "r"(a[1]), "r"(a[2]), "r"(a[3]), "r"(b0), "r"(b1));
}

// ---------------------------------------------------------------------------
// Kernel 1: 4 frames per warp score dots; tail blocks convert w_comb -> g_Wh.
// ---------------------------------------------------------------------------
__global__ void k_score4p(const float* __restrict__ x,
                          const float* __restrict__ wscore,
                          const float* __restrict__ wcomb,
                          int D, int BS, int score_blocks, int do_prep)
{
    if ((int)blockIdx.x >= score_blocks) {
        if (!do_prep) return;
        // W prep: 256 tail blocks x 256 threads x 4 elems = 512*512, plain layout
        int base = ((int)blockIdx.x - score_blocks) * 1024 + threadIdx.x * 4;
        if (base + 3 < 512 * 512) {
            float4 v = *(const float4*)(wcomb + base);
            __half2* dst = (__half2*)(g_Wh + base);
            dst[0] = __floats2half2_rn(v.x, v.y);
            dst[1] = __floats2half2_rn(v.z, v.w);
        }
        return;
    }

    int wrp  = blockIdx.x * 8 + (threadIdx.x >> 5);
    int f0   = wrp * 4;
    if (f0 >= BS) return;
    int lane = threadIdx.x & 31;
    int n4 = D >> 2;

    const float4* w1 = (const float4*)(wscore);
    const float4* w2 = (const float4*)(wscore + D);
    const float4* fr[4];
    bool has[4];
    #pragma unroll
    for (int j = 0; j < 4; j++) {
        has[j] = (f0 + j) < BS;
        fr[j] = (const float4*)(x + (size_t)(f0 + (has[j] ? j : 0)) * D);
    }

    float pa[4] = {0.f, 0.f, 0.f, 0.f};
    float qa[4] = {0.f, 0.f, 0.f, 0.f};
    for (int i = lane; i < n4; i += 32) {
        float4 u = w1[i];
        float4 v = w2[i];
        #pragma unroll
        for (int j = 0; j < 4; j++) {
            float4 xv = fr[j][i];
            pa[j] += xv.x * u.x + xv.y * u.y + xv.z * u.z + xv.w * u.w;
            qa[j] += xv.x * v.x + xv.y * v.y + xv.z * v.z + xv.w * v.w;
        }
    }
    #pragma unroll
    for (int o = 16; o; o >>= 1) {
        #pragma unroll
        for (int j = 0; j < 4; j++) {
            pa[j] += __shfl_xor_sync(0xffffffffu, pa[j], o);
            qa[j] += __shfl_xor_sync(0xffffffffu, qa[j], o);
        }
    }
    if (lane == 0) {
        #pragma unroll
        for (int j = 0; j < 4; j++)
            if (has[j]) { g_p[f0 + j] = pa[j]; g_q[f0 + j] = qa[j]; }
    }
}

// ---------------------------------------------------------------------------
// Kernel 2: per-batch scan of start flags -> word boundaries + n_words.
// ---------------------------------------------------------------------------
__global__ void k_scan(const float* __restrict__ bscore_p,
                       int S, float* __restrict__ tail)
{
    const int T = 256;
    int b   = blockIdx.x;
    int tid = threadIdx.x;
    int chunk = (S + T - 1) / T;
    if (chunk > 16) chunk = 16;

    const float* pb = g_p + (size_t)b * S;
    const float* qb = g_q + (size_t)b * S;
    float bsc = *bscore_p;

    int local[16];
    int sum = 0;
    for (int i = 0; i < chunk; i++) {
        int t = tid * chunk + i;
        int st = 0;
        if (t > 0 && t < S) {
            float sc = pb[t - 1] + qb[t] + bsc;
            st = (sc > 0.5f) ? 0 : 1;
        }
        sum += st;
        local[i] = sum;
    }

    int lane = tid & 31, w = tid >> 5;
    int v = sum;
    #pragma unroll
    for (int o = 1; o < 32; o <<= 1) {
        int n = __shfl_up_sync(0xffffffffu, v, o);
        if (lane >= o) v += n;
    }
    __shared__ int wsum[8];
    __shared__ int woff[9];
    if (lane == 31) wsum[w] = v;
    __syncthreads();
    if (tid == 0) {
        int acc = 0;
        for (int i = 0; i < 8; i++) { woff[i] = acc; acc += wsum[i]; }
        woff[8] = acc;
    }
    __syncthreads();

    int excl = woff[w] + (v - sum);
    int* wsb = g_wstart + (size_t)b * (S + 1);
    for (int i = 0; i < chunk; i++) {
        int t = tid * chunk + i;
        if (t < S) {
            int stflag = local[i] - (i ? local[i - 1] : 0);
            int seg = excl + local[i];
            if (t == 0 || stflag) wsb[seg] = t;
        }
    }
    if (tid == 0) {
        int nw = woff[8] + 1;
        wsb[nw] = S;
        g_nw[b] = nw;
        if (tail) tail[b] = (float)nw;
    }
}

// ---------------------------------------------------------------------------
// Kernel 3: segment mean -> g_Mh (half). TWO words per warp, interleaved.
// ---------------------------------------------------------------------------
__global__ void k_segmean_w2(const float* __restrict__ frame, int S, int BS)
{
    int w0 = (blockIdx.x * 8 + (threadIdx.x >> 5)) * 2;
    if (w0 >= BS) return;
    int w1 = w0 + 1;
    bool has1 = w1 < BS;
    int lane = threadIdx.x & 31;

    int b0 = w0 / S, s0 = w0 - b0 * S;
    int b1 = has1 ? (w1 / S) : b0;
    int s1 = has1 ? (w1 - b1 * S) : 0;

    bool v0 = s0 < g_nw[b0];
    bool v1 = has1 && (s1 < g_nw[b1]);

    int st0 = 0, en0 = 0, st1 = 0, en1 = 0;
    if (v0) {
        const int* wsb = g_wstart + (size_t)b0 * (S + 1);
        st0 = wsb[s0]; en0 = wsb[s0 + 1];
    }
    if (v1) {
        const int* wsb = g_wstart + (size_t)b1 * (S + 1);
        st1 = wsb[s1]; en1 = wsb[s1 + 1];
    }
    int len0 = en0 - st0, len1 = en1 - st1;
    int L = len0 > len1 ? len0 : len1;
    if (L == 0) return;

    const float4* f0 = (const float4*)(frame + ((size_t)b0 * S) * 512);
    const float4* f1 = (const float4*)(frame + ((size_t)b1 * S) * 512);

    float4 a0[4], a1[4];
    #pragma unroll
    for (int j = 0; j < 4; j++) {
        a0[j] = make_float4(0.f, 0.f, 0.f, 0.f);
        a1[j] = make_float4(0.f, 0.f, 0.f, 0.f);
    }

    for (int i = 0; i < L; i++) {
        if (i < len0) {
            const float4* row = f0 + (size_t)(st0 + i) * 128;
            #pragma unroll
            for (int j = 0; j < 4; j++) {
                float4 v = row[lane + j * 32];
                a0[j].x += v.x; a0[j].y += v.y; a0[j].z += v.z; a0[j].w += v.w;
            }
        }
        if (i < len1) {
            const float4* row = f1 + (size_t)(st1 + i) * 128;
            #pragma unroll
            for (int j = 0; j < 4; j++) {
                float4 v = row[lane + j * 32];
                a1[j].x += v.x; a1[j].y += v.y; a1[j].z += v.z; a1[j].w += v.w;
            }
        }
    }

    if (v0) {
        float inv = 1.f / (float)len0;
        __half2* mr = (__half2*)(g_Mh + (size_t)w0 * 512);
        #pragma unroll
        for (int j = 0; j < 4; j++) {
            int i = lane + j * 32;
            mr[i * 2]     = __floats2half2_rn(a0[j].x * inv, a0[j].y * inv);
            mr[i * 2 + 1] = __floats2half2_rn(a0[j].z * inv, a0[j].w * inv);
        }
    }
    if (v1) {
        float inv = 1.f / (float)len1;
        __half2* mr = (__half2*)(g_Mh + (size_t)w1 * 512);
        #pragma unroll
        for (int j = 0; j < 4; j++) {
            int i = lane + j * 32;
            mr[i * 2]     = __floats2half2_rn(a1[j].x * inv, a1[j].y * inv);
            mr[i * 2 + 1] = __floats2half2_rn(a1[j].z * inv, a1[j].w * inv);
        }
    }
}

// ---------------------------------------------------------------------------
// Kernel 4: mma.sync f16 GEMM, 4-stage cp.async, dual-ldmatrix, 2-set pipeline.
// out[BS,512] = Mh[BS,512] @ W[512,512] (+bias, mask).
// Smem A: [128][56] halves (112B stride).
// Smem B: [32][136] halves (272B row stride) plain [k][n] -> ldsm.trans OK.
// ---------------------------------------------------------------------------
#define MH_ASTRIDE 56
#define MH_ABYTES  (128 * MH_ASTRIDE * 2)       // 14336
#define MH_BROW    136
#define MH_BBYTES  (32 * MH_BROW * 2)           // 8704
#define MH_STAGE   (MH_ABYTES + MH_BBYTES)      // 23040
#define MH_NSTAGE  4
#define MH_SMEM    (MH_NSTAGE * MH_STAGE)       // 92160

__device__ __forceinline__ void mh_load(uint32_t base, int stage,
                                        long m0, int n0, int k0, int tid)
{
    uint32_t a_s = base + (uint32_t)stage * MH_STAGE;
    uint32_t b_s = a_s + MH_ABYTES;
    #pragma unroll
    for (int j = 0; j < 2; j++) {                // A: 128 rows x 32 halves (64B)
        int L = tid + 256 * j;
        int row = L >> 2, seg = L & 3;
        cp16(a_s + (uint32_t)row * (MH_ASTRIDE * 2) + (uint32_t)seg * 16,
             g_Mh + (m0 + row) * 512 + k0 + seg * 8);
    }
    #pragma unroll
    for (int j = 0; j < 2; j++) {                // B: 32 k-rows x 128 halves (256B)
        int L = tid + 256 * j;
        int row = L >> 4, seg = L & 15;
        cp16(b_s + (uint32_t)row * (MH_BROW * 2) + (uint32_t)seg * 16,
             g_Wh + (size_t)(k0 + row) * 512 + n0 + seg * 8);
    }
    asm volatile("cp.async.commit_group;" ::: "memory");
}

__global__ __launch_bounds__(256, 2)
void k_tgemm_mma(const float* __restrict__ bcomb,
                 float* __restrict__ out, int S)
{
    extern __shared__ char smem[];
    uint32_t base = smem_u32(smem);

    int tid  = threadIdx.x;
    long m0 = (long)blockIdx.y * 128;
    int  n0 = blockIdx.x * 128;

    // ---- fully-invalid tile: zero-fill our column strip and exit ----
    {
        int b0 = (int)(m0 / S);
        int s0 = (int)(m0 - (long)b0 * S);
        if (s0 + 128 <= S && s0 >= g_nw[b0]) {
            float4 z = make_float4(0.f, 0.f, 0.f, 0.f);
            #pragma unroll
            for (int j = 0; j < 16; j++) {
                int L = tid + 256 * j;              // 4096 float4 slots
                int row = L >> 5, seg = L & 31;
                *(float4*)(out + (m0 + row) * 512 + n0 + seg * 4) = z;
            }
            return;
        }
    }

    int lane = tid & 31;
    int wid  = tid >> 5;
    int wm   = wid & 1;          // 0/1 -> 64-row half
    int wn   = wid >> 1;         // 0..3 -> 32-col quarter
    int g    = lane >> 2;        // groupID
    int t    = lane & 3;         // threadID_in_group

    // ldmatrix lane addr (A fragment, m16n8k16 row-major)
    int lm_tile   = lane >> 3;
    int lm_rowoff = (lane & 7) + ((lm_tile & 1) << 3);
    int lm_koff   = (lm_tile >> 1) << 3;
    uint32_t lm_lane_b = (uint32_t)((wm * 64 + lm_rowoff) * (MH_ASTRIDE * 2)
                                    + lm_koff * 2);

    // ldmatrix.trans lane addr (B fragment): tiles (k-oct, n-oct) =
    // t0=(0,0) t1=(1,0) t2=(0,1) t3=(1,1)
    int bl_k = (lane & 7) + ((lm_tile & 1) << 3);
    int bl_n = (lm_tile >> 1) << 3;
    uint32_t bs_lane = (uint32_t)(bl_k * (MH_BROW * 2) + (wn * 32 + bl_n) * 2);

    float c[4][4][4];
    #pragma unroll
    for (int i = 0; i < 4; i++)
        #pragma unroll
        for (int j = 0; j < 4; j++)
            #pragma unroll
            for (int r = 0; r < 4; r++) c[i][j][r] = 0.f;

    // prologue: 3 stages in flight
    mh_load(base, 0, m0, n0, 0, tid);
    mh_load(base, 1, m0, n0, 32, tid);
    mh_load(base, 2, m0, n0, 64, tid);

    #pragma unroll 1
    for (int ch = 0; ch < 16; ch++) {
        if (ch <= 13)      asm volatile("cp.async.wait_group 2;" ::: "memory");
        else if (ch == 14) asm volatile("cp.async.wait_group 1;" ::: "memory");
        else               asm volatile("cp.async.wait_group 0;" ::: "memory");
        __syncthreads();

        if (ch + 3 < 16)
            mh_load(base, (ch + 3) & 3, m0, n0, (ch + 3) * 32, tid);

        uint32_t a_stage = base + (uint32_t)(ch & 3) * MH_STAGE;
        uint32_t a_lm    = a_stage + lm_lane_b;
        uint32_t b_lm    = a_stage + MH_ABYTES + bs_lane;

        // ---- load BOTH kk-sets before any MMA (latency hiding) ----
        uint32_t af0[4][4], af1[4][4];
        uint32_t bq0[2][4], bq1[2][4];
        #pragma unroll
        for (int mt = 0; mt < 4; mt++)
            ldsm_x4(af0[mt], a_lm + (uint32_t)(mt * 16 * (MH_ASTRIDE * 2)));
        ldsm_x4_t(bq0[0], b_lm);
        ldsm_x4_t(bq0[1], b_lm + 32);                 // +16 cols
        #pragma unroll
        for (int mt = 0; mt < 4; mt++)
            ldsm_x4(af1[mt], a_lm + (uint32_t)(mt * 16 * (MH_ASTRIDE * 2) + 32));
        ldsm_x4_t(bq1[0], b_lm + 16 * (MH_BROW * 2));  // +16 k-rows
        ldsm_x4_t(bq1[1], b_lm + 16 * (MH_BROW * 2) + 32);

        #pragma unroll
        for (int mt = 0; mt < 4; mt++)
            #pragma unroll
            for (int nt = 0; nt < 4; nt++)
                mma_f16(c[mt][nt], af0[mt],
                        bq0[nt >> 1][(nt & 1) * 2], bq0[nt >> 1][(nt & 1) * 2 + 1]);
        #pragma unroll
        for (int mt = 0; mt < 4; mt++)
            #pragma unroll
            for (int nt = 0; nt < 4; nt++)
                mma_f16(c[mt][nt], af1[mt],
                        bq1[nt >> 1][(nt & 1) * 2], bq1[nt >> 1][(nt & 1) * 2 + 1]);
    }

    // epilogue: bias + validity mask, float2 stores
    #pragma unroll
    for (int mt = 0; mt < 4; mt++) {
        #pragma unroll
        for (int half = 0; half < 2; half++) {
            long grow = m0 + wm * 64 + mt * 16 + g + half * 8;
            int b = (int)(grow / S);
            int s = (int)(grow - (long)b * S);
            bool valid = s < g_nw[b];
            float* orow = out + grow * 512 + n0;
            #pragma unroll
            for (int nt = 0; nt < 4; nt++) {
                int col = wn * 32 + nt * 8 + t * 2;
                float2 v;
                if (valid) {
                    v.x = c[mt][nt][half * 2 + 0] + bcomb[n0 + col];
                    v.y = c[mt][nt][half * 2 + 1] + bcomb[n0 + col + 1];
                } else {
                    v.x = 0.f; v.y = 0.f;
                }
                *(float2*)(orow + col) = v;
            }
        }
    }
}

// ---------------------------------------------------------------------------
// Fallback SIMT path (D != 512): fp32 SGEMM + segment-average.
// ---------------------------------------------------------------------------
#define BM 128
#define BN 128
#define BK 8
__global__ __launch_bounds__(256, 2)
void k_gemm(const float* __restrict__ A, const float* __restrict__ Wm,
            int M, int N, int K)
{
    __shared__ float As[2][BK][BM];
    __shared__ float Bs[2][BK][BN];
    int bx = blockIdx.x, by = blockIdx.y;
    int tid = threadIdx.x;
    int tx = tid & 15, ty = tid >> 4;
    int arow = tid >> 1, acol = (tid & 1) * 4;
    int brow = tid >> 5, bcol = (tid & 31) * 4;
    const float* Ap = A + ((size_t)(by * BM + arow)) * K + acol;
    const float* Bp = Wm + (size_t)brow * N + bx * BN + bcol;

    float acc[8][8];
    #pragma unroll
    for (int i = 0; i < 8; i++)
        #pragma unroll
        for (int j = 0; j < 8; j++) acc[i][j] = 0.f;

    float4 a4 = *(const float4*)Ap;
    float4 b4 = *(const float4*)Bp;
    As[0][acol + 0][arow] = a4.x; As[0][acol + 1][arow] = a4.y;
    As[0][acol + 2][arow] = a4.z; As[0][acol + 3][arow] = a4.w;
    *(float4*)&Bs[0][brow][bcol] = b4;
    __syncthreads();

    int buf = 0;
    for (int k0 = 0; k0 < K; k0 += BK) {
        bool more = (k0 + BK) < K;
        float4 na, nb;
        if (more) {
            na = *(const float4*)(Ap + (k0 + BK));
            nb = *(const float4*)(Bp + (size_t)(k0 + BK) * N);
        }
        #pragma unroll
        for (int k = 0; k < BK; k++) {
            float ra[8], rb[8];
            *(float4*)(ra + 0) = *(float4*)&As[buf][k][ty * 4];
            *(float4*)(ra + 4) = *(float4*)&As[buf][k][64 + ty * 4];
            *(float4*)(rb + 0) = *(float4*)&Bs[buf][k][tx * 4];
            *(float4*)(rb + 4) = *(float4*)&Bs[buf][k][64 + tx * 4];
            #pragma unroll
            for (int i = 0; i < 8; i++)
                #pragma unroll
                for (int j = 0; j < 8; j++)
                    acc[i][j] = fmaf(ra[i], rb[j], acc[i][j]);
        }
        if (more) {
            int nxt = buf ^ 1;
            As[nxt][acol + 0][arow] = na.x; As[nxt][acol + 1][arow] = na.y;
            As[nxt][acol + 2][arow] = na.z; As[nxt][acol + 3][arow] = na.w;
            *(float4*)&Bs[nxt][brow][bcol] = nb;
            __syncthreads();
            buf = nxt;
        }
    }
    #pragma unroll
    for (int i = 0; i < 8; i++) {
        int r = by * BM + ((i < 4) ? (ty * 4 + i) : (64 + ty * 4 + i - 4));
        float* crow = g_Y + (size_t)r * N + bx * BN;
        *(float4*)(crow + tx * 4)      = make_float4(acc[i][0], acc[i][1], acc[i][2], acc[i][3]);
        *(float4*)(crow + 64 + tx * 4) = make_float4(acc[i][4], acc[i][5], acc[i][6], acc[i][7]);
    }
}

__global__ void k_avg(const float* __restrict__ bcomb,
                      float* __restrict__ out, int S, int D)
{
    int b = blockIdx.y, s = blockIdx.x;
    int n4 = D >> 2;
    float4* orow = (float4*)(out + ((size_t)b * S + s) * D);
    int nw = g_nw[b];
    if (s >= nw) {
        for (int i = threadIdx.x; i < n4; i += blockDim.x)
            orow[i] = make_float4(0.f, 0.f, 0.f, 0.f);
        return;
    }
    const int* wsb = g_wstart + (size_t)b * (S + 1);
    int st = wsb[s], en = wsb[s + 1];
    float inv = 1.f / (float)(en - st);
    const float4* ybase = (const float4*)(g_Y + ((size_t)b * S) * D);
    const float4* bc4 = (const float4*)bcomb;
    for (int i = threadIdx.x; i < n4; i += blockDim.x) {
        float4 acc = make_float4(0.f, 0.f, 0.f, 0.f);
        for (int tt = st; tt < en; tt++) {
            float4 v = ybase[(size_t)tt * n4 + i];
            acc.x += v.x; acc.y += v.y; acc.z += v.z; acc.w += v.w;
        }
        float4 bb = bc4[i];
        orow[i] = make_float4(acc.x * inv + bb.x, acc.y * inv + bb.y,
                              acc.z * inv + bb.z, acc.w * inv + bb.w);
    }
}

// ---------------------------------------------------------------------------
extern "C" void kernel_launch(void* const* d_in, const int* in_sizes, int n_in,
                              void* d_out, int out_size)
{
    const float* frame  = (const float*)d_in[0];
    const float* wscore = (const float*)d_in[1];
    const float* bscore = (const float*)d_in[2];
    const float* wcomb  = (const float*)d_in[3];
    const float* bcomb  = (const float*)d_in[4];
    float* out = (float*)d_out;

    int D   = in_sizes[1] / 2;
    long total = in_sizes[0];
    int BS  = (int)(total / D);

    int B = out_size - (int)total;
    if (B <= 0 || B > MAX_B || (BS % B) != 0) {
        B = 16;
        while (B > 1 && (BS % B) != 0) B >>= 1;
    }
    int S = BS / B;
    float* tail = (out_size == (int)total + B) ? (out + total) : nullptr;

    bool tpath = (D == 512 && (BS % 128) == 0);

    // 1) score dots (4 frames/warp) + merged W-prep tail blocks
    {
        int score_blocks = (BS + 31) / 32;
        int prep_blocks  = tpath ? 256 : 0;
        k_score4p<<<score_blocks + prep_blocks, 256>>>(
            frame, wscore, wcomb, D, BS, score_blocks, tpath ? 1 : 0);
    }
    // 2) per-batch scan
    k_scan<<<B, 256>>>(bscore, S, tail);

    if (tpath) {
        // --- tensor path (mma.sync m16n8k16 f16) ---
        k_segmean_w2<<<(BS / 2 + 7) / 8, 256>>>(frame, S, BS);
        static int smem_set = 0;
        if (!smem_set) {
            cudaFuncSetAttribute(k_tgemm_mma,
                                 cudaFuncAttributeMaxDynamicSharedMemorySize, MH_SMEM);
            smem_set = 1;
        }
        dim3 grid(512 / 128, BS / 128);
        k_tgemm_mma<<<grid, 256, MH_SMEM>>>(bcomb, out, S);
    } else {
        // --- fallback SIMT path ---
        dim3 grid(D / BN, BS / BM);
        k_gemm<<<grid, 256>>>(frame, wcomb, BS, D, D);
        dim3 agrid(S, B);
        k_avg<<<agrid, 128>>>(bcomb, out, S, D);
    }
}